// round 4
// baseline (speedup 1.0000x reference)
#include <cuda_runtime.h>
#include <math.h>

#define NMAX 50000
#define EMAX 1600000
#define D 128
#define T 8
#define RP 10   // padded smem row stride (floats): 8B-aligned for LDS.64

// ---- scratch (static device globals; no allocation anywhere) ----
__device__ float g_buf[2][2][NMAX * D];      // [graph][ping-pong][N*D]
__device__ int   g_deg[2][NMAX];
__device__ int   g_rowstart[2][NMAX + 1];
__device__ int   g_cursor[2][NMAX];
__device__ int   g_csr[2][EMAX];
__device__ float g_invdeg[2][NMAX];
__device__ float g_colsum[2 * D];

// ---- f32x2 packed helpers ----
__device__ __forceinline__ unsigned long long pack2(float lo, float hi) {
    unsigned long long r;
    asm("mov.b64 %0, {%1, %2};" : "=l"(r) : "f"(lo), "f"(hi));
    return r;
}
__device__ __forceinline__ void unpack2(unsigned long long v, float& lo, float& hi) {
    asm("mov.b64 {%0, %1}, %2;" : "=f"(lo), "=f"(hi) : "l"(v));
}
__device__ __forceinline__ unsigned long long fma2(unsigned long long a,
                                                   unsigned long long b,
                                                   unsigned long long c) {
    unsigned long long d;
    asm("fma.rn.f32x2 %0, %1, %2, %3;" : "=l"(d) : "l"(a), "l"(b), "l"(c));
    return d;
}

// ---------------- init: zero degrees (both graphs) + colsum ----------------
__global__ void k_init(int n) {
    int gi = blockIdx.y;
    int i = blockIdx.x * blockDim.x + threadIdx.x;
    if (i < n) g_deg[gi][i] = 0;
    if (gi == 0 && blockIdx.x == 0 && threadIdx.x < 2 * D) g_colsum[threadIdx.x] = 0.f;
}

// ---------------- degree count (both graphs) ----------------
__global__ void k_count(const int* __restrict__ d0, const int* __restrict__ d1,
                        int e0, int e1) {
    int gi = blockIdx.y;
    const int* __restrict__ dst = gi ? d1 : d0;
    int e = gi ? e1 : e0;
    int i = blockIdx.x * blockDim.x + threadIdx.x;
    if (i < e) atomicAdd(&g_deg[gi][dst[i]], 1);
}

// ---------------- fast exclusive scan: 1 block per graph, warp shuffles ----------------
__global__ void k_scan(int n) {
    int gi = blockIdx.x;
    const int* __restrict__ deg = g_deg[gi];
    int* __restrict__ rowstart = g_rowstart[gi];
    int* __restrict__ cursor = g_cursor[gi];
    float* __restrict__ invdeg = g_invdeg[gi];

    __shared__ int s_warp[32];
    __shared__ int s_carry;
    int tid = threadIdx.x;
    int lane = tid & 31;
    int wid = tid >> 5;
    if (tid == 0) s_carry = 0;
    __syncthreads();

    for (int base = 0; base < n; base += 1024) {
        int i = base + tid;
        int v = (i < n) ? deg[i] : 0;
        int s = v;
        #pragma unroll
        for (int d = 1; d < 32; d <<= 1) {
            int t = __shfl_up_sync(0xffffffffu, s, d);
            if (lane >= d) s += t;
        }
        if (lane == 31) s_warp[wid] = s;
        __syncthreads();
        if (wid == 0) {
            int w = s_warp[lane];
            #pragma unroll
            for (int d = 1; d < 32; d <<= 1) {
                int t = __shfl_up_sync(0xffffffffu, w, d);
                if (lane >= d) w += t;
            }
            s_warp[lane] = w;
        }
        __syncthreads();
        int carry = s_carry;
        int excl = carry + (wid ? s_warp[wid - 1] : 0) + s - v;
        if (i < n) {
            rowstart[i] = excl;
            cursor[i]   = excl;
            invdeg[i]   = 1.0f / fmaxf((float)v, 1.0f);
        }
        __syncthreads();
        if (tid == 0) s_carry = carry + s_warp[31];
        __syncthreads();
    }
    if (tid == 0) rowstart[n] = s_carry;
}

// ---------------- CSR fill (both graphs) ----------------
__global__ void k_fill(const int* __restrict__ s0, const int* __restrict__ d0,
                       const int* __restrict__ s1, const int* __restrict__ d1,
                       int e0, int e1) {
    int gi = blockIdx.y;
    const int* __restrict__ src = gi ? s1 : s0;
    const int* __restrict__ dst = gi ? d1 : d0;
    int e = gi ? e1 : e0;
    int i = blockIdx.x * blockDim.x + threadIdx.x;
    if (i < e) {
        int p = atomicAdd(&g_cursor[gi][dst[i]], 1);
        g_csr[gi][p] = src[i];
    }
}

// ---------------- fused aggregate (mean, float4 gathers) + GEMM + bias ----------------
// block = 128 threads = 4 warps; warp w aggregates nodes {2w, 2w+1} via LDG.128;
// GEMM phase: thread tid = output feature, f32x2 packed FMAs over smem rows[k][t].
// If colsum != nullptr, also atomically accumulate per-feature column sums (readout).
__global__ void __launch_bounds__(128, 12) k_layer(
    const float* __restrict__ feat, int gi, int sel_in, int sel_out,
    const float* __restrict__ W, const float* __restrict__ bias, int n,
    float* __restrict__ colsum)
{
    const float* __restrict__ h_in  = (sel_in < 0) ? feat : g_buf[gi][sel_in];
    float* __restrict__       h_out = g_buf[gi][sel_out];
    const int* __restrict__ rowstart = g_rowstart[gi];
    const int* __restrict__ csr = g_csr[gi];
    const float* __restrict__ invdeg = g_invdeg[gi];

    __shared__ float rows[D][RP];   // [k][t]
    int tid  = threadIdx.x;
    int lane = tid & 31;
    int w    = tid >> 5;
    int base = blockIdx.x * T;

    // ---- aggregation: warp w handles nodes base+2w, base+2w+1; lane covers feats [4L,4L+4) ----
    #pragma unroll
    for (int tt = 0; tt < 2; tt++) {
        int t = 2 * w + tt;
        int node = base + t;
        float4 acc = make_float4(0.f, 0.f, 0.f, 0.f);
        if (node < n) {
            int s = rowstart[node];
            int e = rowstart[node + 1];
            float4 a0 = acc, a1 = acc, a2 = acc, a3 = acc;
            int i = s;
            for (; i + 4 <= e; i += 4) {
                int c0 = csr[i], c1 = csr[i + 1], c2 = csr[i + 2], c3 = csr[i + 3];
                float4 v0 = __ldcg((const float4*)&h_in[(size_t)c0 * D + 4 * lane]);
                float4 v1 = __ldcg((const float4*)&h_in[(size_t)c1 * D + 4 * lane]);
                float4 v2 = __ldcg((const float4*)&h_in[(size_t)c2 * D + 4 * lane]);
                float4 v3 = __ldcg((const float4*)&h_in[(size_t)c3 * D + 4 * lane]);
                a0.x += v0.x; a0.y += v0.y; a0.z += v0.z; a0.w += v0.w;
                a1.x += v1.x; a1.y += v1.y; a1.z += v1.z; a1.w += v1.w;
                a2.x += v2.x; a2.y += v2.y; a2.z += v2.z; a2.w += v2.w;
                a3.x += v3.x; a3.y += v3.y; a3.z += v3.z; a3.w += v3.w;
            }
            for (; i < e; i++) {
                float4 v = __ldcg((const float4*)&h_in[(size_t)csr[i] * D + 4 * lane]);
                a0.x += v.x; a0.y += v.y; a0.z += v.z; a0.w += v.w;
            }
            float id = invdeg[node];
            acc.x = ((a0.x + a1.x) + (a2.x + a3.x)) * id;
            acc.y = ((a0.y + a1.y) + (a2.y + a3.y)) * id;
            acc.z = ((a0.z + a1.z) + (a2.z + a3.z)) * id;
            acc.w = ((a0.w + a1.w) + (a2.w + a3.w)) * id;
        }
        // transpose-store into rows[k][t] (4 conflicted STS.32 — cheap, one-time)
        rows[4 * lane + 0][t] = acc.x;
        rows[4 * lane + 1][t] = acc.y;
        rows[4 * lane + 2][t] = acc.z;
        rows[4 * lane + 3][t] = acc.w;
    }
    __syncthreads();

    // ---- GEMM: out[node][tid] = sum_k rows[k][node] * W[k][tid] + b[tid] ----
    float bv = bias[tid];
    unsigned long long acc01 = pack2(bv, bv);
    unsigned long long acc23 = acc01, acc45 = acc01, acc67 = acc01;

    #pragma unroll 4
    for (int k = 0; k < D; k++) {
        float wv = W[k * D + tid];
        unsigned long long w2 = pack2(wv, wv);
        const unsigned long long* rp = (const unsigned long long*)&rows[k][0];
        acc01 = fma2(rp[0], w2, acc01);
        acc23 = fma2(rp[1], w2, acc23);
        acc45 = fma2(rp[2], w2, acc45);
        acc67 = fma2(rp[3], w2, acc67);
    }

    float o[T];
    unpack2(acc01, o[0], o[1]);
    unpack2(acc23, o[2], o[3]);
    unpack2(acc45, o[4], o[5]);
    unpack2(acc67, o[6], o[7]);

    float csum = 0.f;
    #pragma unroll
    for (int t = 0; t < T; t++) {
        int node = base + t;
        if (node < n) {
            h_out[(size_t)node * D + tid] = o[t];
            csum += o[t];
        }
    }
    if (colsum) atomicAdd(&colsum[tid], csum);   // fused readout column-sum
}

// ---------------- final: readout MLP + match MLP + sigmoid ----------------
__global__ void k_match(const float* __restrict__ Wr,  const float* __restrict__ br,
                        const float* __restrict__ Wm1, const float* __restrict__ bm1,
                        const float* __restrict__ Wm2, const float* __restrict__ bm2,
                        float n_nodes, float* __restrict__ out)
{
    __shared__ float c[2 * D];
    __shared__ float red[D];
    int tid = threadIdx.x;          // 256 threads
    int g = tid / D;
    int j = tid % D;
    float invn = 1.0f / n_nodes;

    float acc = br[j];
    for (int k = 0; k < D; k++)
        acc += (g_colsum[g * D + k] * invn) * Wr[k * D + j];
    c[tid] = 1.0f / (1.0f + expf(-acc));    // g_p / g_s concatenated
    __syncthreads();

    if (tid < D) {
        float d1 = bm1[tid];
        for (int i = 0; i < 2 * D; i++)
            d1 += c[i] * Wm1[i * D + tid];
        red[tid] = d1 * Wm2[tid];
    }
    __syncthreads();

    if (tid == 0) {
        float s = 0.f;
        for (int i = 0; i < D; i++) s += red[i];
        out[0] = 1.0f / (1.0f + expf(-(s + bm2[0])));
    }
}

// ---------------- launch ----------------
extern "C" void kernel_launch(void* const* d_in, const int* in_sizes, int n_in,
                              void* d_out, int out_size)
{
    const float* feat_p = (const float*)d_in[0];
    const int*   src_p  = (const int*)d_in[1];
    const int*   dst_p  = (const int*)d_in[2];
    const float* feat_s = (const float*)d_in[3];
    const int*   src_s  = (const int*)d_in[4];
    const int*   dst_s  = (const int*)d_in[5];
    const float* W[3]   = { (const float*)d_in[6], (const float*)d_in[8], (const float*)d_in[10] };
    const float* b[3]   = { (const float*)d_in[7], (const float*)d_in[9], (const float*)d_in[11] };
    const float* Wr  = (const float*)d_in[12];
    const float* br  = (const float*)d_in[13];
    const float* Wm1 = (const float*)d_in[14];
    const float* bm1 = (const float*)d_in[15];
    const float* Wm2 = (const float*)d_in[16];
    const float* bm2 = (const float*)d_in[17];

    int n  = in_sizes[0] / D;
    int e0 = in_sizes[1];
    int e1 = in_sizes[4];
    int emax = e0 > e1 ? e0 : e1;

    dim3 gN((n + 511) / 512, 2);
    dim3 gE((emax + 511) / 512, 2);

    k_init<<<gN, 512>>>(n);
    k_count<<<gE, 512>>>(dst_p, dst_s, e0, e1);
    k_scan<<<2, 1024>>>(n);
    k_fill<<<gE, 512>>>(src_p, dst_p, src_s, dst_s, e0, e1);

    int nb = (n + T - 1) / T;
    // graphs sequential: keeps per-launch working set (~58 MB) L2-resident
    k_layer<<<nb, 128>>>(feat_p, 0, -1, 0, W[0], b[0], n, nullptr);
    k_layer<<<nb, 128>>>(feat_p, 0,  0, 1, W[1], b[1], n, nullptr);
    k_layer<<<nb, 128>>>(feat_p, 0,  1, 0, W[2], b[2], n, &g_colsum[0]);
    k_layer<<<nb, 128>>>(feat_s, 1, -1, 0, W[0], b[0], n, nullptr);
    k_layer<<<nb, 128>>>(feat_s, 1,  0, 1, W[1], b[1], n, nullptr);
    k_layer<<<nb, 128>>>(feat_s, 1,  1, 0, W[2], b[2], n, &g_colsum[D]);

    k_match<<<1, 256>>>(Wr, br, Wm1, bm1, Wm2, bm2, (float)n, (float*)d_out);
}

// round 5
// speedup vs baseline: 2.5720x; 2.5720x over previous
#include <cuda_runtime.h>
#include <math.h>

#define NMAX 50000
#define EMAX 1600000
#define D 128
#define T 8
#define RP 12   // padded smem row stride (floats): 48B per row -> 16B-aligned LDS.128

// ---- scratch (static device globals; no allocation anywhere) ----
__device__ float g_buf[2][2][NMAX * D];      // [graph][ping-pong][N*D]
__device__ int   g_deg[2][NMAX];
__device__ int   g_rowstart[2][NMAX + 1];
__device__ int   g_cursor[2][NMAX];
__device__ int   g_csr[2][EMAX];
__device__ float g_invdeg[2][NMAX];
__device__ float g_colsum[2 * D];

// ---- f32x2 packed helpers ----
__device__ __forceinline__ unsigned long long pack2(float lo, float hi) {
    unsigned long long r;
    asm("mov.b64 %0, {%1, %2};" : "=l"(r) : "f"(lo), "f"(hi));
    return r;
}
__device__ __forceinline__ void unpack2(unsigned long long v, float& lo, float& hi) {
    asm("mov.b64 {%0, %1}, %2;" : "=f"(lo), "=f"(hi) : "l"(v));
}
__device__ __forceinline__ unsigned long long fma2(unsigned long long a,
                                                   unsigned long long b,
                                                   unsigned long long c) {
    unsigned long long d;
    asm("fma.rn.f32x2 %0, %1, %2, %3;" : "=l"(d) : "l"(a), "l"(b), "l"(c));
    return d;
}

// ---------------- init: zero degrees (both graphs) + colsum ----------------
__global__ void k_init(int n) {
    int gi = blockIdx.y;
    int i = blockIdx.x * blockDim.x + threadIdx.x;
    if (i < n) g_deg[gi][i] = 0;
    if (gi == 0 && blockIdx.x == 0 && threadIdx.x < 2 * D) g_colsum[threadIdx.x] = 0.f;
}

// ---------------- degree count (both graphs) ----------------
__global__ void k_count(const int* __restrict__ d0, const int* __restrict__ d1,
                        int e0, int e1) {
    int gi = blockIdx.y;
    const int* __restrict__ dst = gi ? d1 : d0;
    int e = gi ? e1 : e0;
    int i = blockIdx.x * blockDim.x + threadIdx.x;
    if (i < e) atomicAdd(&g_deg[gi][dst[i]], 1);
}

// ---------------- fast exclusive scan: 1 block per graph, warp shuffles ----------------
__global__ void k_scan(int n) {
    int gi = blockIdx.x;
    const int* __restrict__ deg = g_deg[gi];
    int* __restrict__ rowstart = g_rowstart[gi];
    int* __restrict__ cursor = g_cursor[gi];
    float* __restrict__ invdeg = g_invdeg[gi];

    __shared__ int s_warp[32];
    __shared__ int s_carry;
    int tid = threadIdx.x;
    int lane = tid & 31;
    int wid = tid >> 5;
    if (tid == 0) s_carry = 0;
    __syncthreads();

    for (int base = 0; base < n; base += 1024) {
        int i = base + tid;
        int v = (i < n) ? deg[i] : 0;
        int s = v;
        #pragma unroll
        for (int d = 1; d < 32; d <<= 1) {
            int t = __shfl_up_sync(0xffffffffu, s, d);
            if (lane >= d) s += t;
        }
        if (lane == 31) s_warp[wid] = s;
        __syncthreads();
        if (wid == 0) {
            int w = s_warp[lane];
            #pragma unroll
            for (int d = 1; d < 32; d <<= 1) {
                int t = __shfl_up_sync(0xffffffffu, w, d);
                if (lane >= d) w += t;
            }
            s_warp[lane] = w;
        }
        __syncthreads();
        int carry = s_carry;
        int excl = carry + (wid ? s_warp[wid - 1] : 0) + s - v;
        if (i < n) {
            rowstart[i] = excl;
            cursor[i]   = excl;
            invdeg[i]   = 1.0f / fmaxf((float)v, 1.0f);
        }
        __syncthreads();
        if (tid == 0) s_carry = carry + s_warp[31];
        __syncthreads();
    }
    if (tid == 0) rowstart[n] = s_carry;
}

// ---------------- CSR fill (both graphs) ----------------
__global__ void k_fill(const int* __restrict__ s0, const int* __restrict__ d0,
                       const int* __restrict__ s1, const int* __restrict__ d1,
                       int e0, int e1) {
    int gi = blockIdx.y;
    const int* __restrict__ src = gi ? s1 : s0;
    const int* __restrict__ dst = gi ? d1 : d0;
    int e = gi ? e1 : e0;
    int i = blockIdx.x * blockDim.x + threadIdx.x;
    if (i < e) {
        int p = atomicAdd(&g_cursor[gi][dst[i]], 1);
        g_csr[gi][p] = src[i];
    }
}

// ---------------- fused aggregate (mean, float2 gathers) + GEMM + bias ----------------
// 128 threads: thread = (column-pair c2 in [0,64), node-group g in {0,1}).
// Aggregation: thread owns cols {2c2, 2c2+1} of 4 nodes (g*4..g*4+3) — LDG.64 gathers.
// GEMM: thread tid = output feature; f32x2 packed FMAs, LDS.128 row loads.
// cs >= 0: also accumulate per-feature column sums into g_colsum[cs*D + tid].
__global__ void __launch_bounds__(128, 8) k_layer(
    const float* __restrict__ feat, int gi, int sel_in, int sel_out,
    const float* __restrict__ W, const float* __restrict__ bias, int n, int cs)
{
    const float* __restrict__ h_in  = (sel_in < 0) ? feat : g_buf[gi][sel_in];
    float* __restrict__       h_out = g_buf[gi][sel_out];
    const int* __restrict__ rowstart = g_rowstart[gi];
    const int* __restrict__ csr = g_csr[gi];
    const float* __restrict__ invdeg = g_invdeg[gi];

    __shared__ float rows[D][RP];   // [k][t], 48B row stride (16B aligned)
    int tid = threadIdx.x;
    int c2  = tid & 63;             // column pair: cols {2c2, 2c2+1}
    int g   = tid >> 6;             // node half: nodes base+4g .. base+4g+3
    int base = blockIdx.x * T;

    #pragma unroll
    for (int t = 0; t < 4; t++) {
        int node = base + g * 4 + t;
        float accx = 0.f, accy = 0.f;
        if (node < n) {
            int s = rowstart[node];
            int e = rowstart[node + 1];
            float a0x = 0.f, a0y = 0.f, a1x = 0.f, a1y = 0.f;
            float a2x = 0.f, a2y = 0.f, a3x = 0.f, a3y = 0.f;
            int i = s;
            for (; i + 4 <= e; i += 4) {
                int c0 = csr[i], c1 = csr[i + 1], cc = csr[i + 2], c3 = csr[i + 3];
                float2 v0 = __ldcg((const float2*)&h_in[(size_t)c0 * D + 2 * c2]);
                float2 v1 = __ldcg((const float2*)&h_in[(size_t)c1 * D + 2 * c2]);
                float2 v2 = __ldcg((const float2*)&h_in[(size_t)cc * D + 2 * c2]);
                float2 v3 = __ldcg((const float2*)&h_in[(size_t)c3 * D + 2 * c2]);
                a0x += v0.x; a0y += v0.y;
                a1x += v1.x; a1y += v1.y;
                a2x += v2.x; a2y += v2.y;
                a3x += v3.x; a3y += v3.y;
            }
            for (; i < e; i++) {
                float2 v = __ldcg((const float2*)&h_in[(size_t)csr[i] * D + 2 * c2]);
                a0x += v.x; a0y += v.y;
            }
            float id = invdeg[node];
            accx = ((a0x + a1x) + (a2x + a3x)) * id;
            accy = ((a0y + a1y) + (a2y + a3y)) * id;
        }
        rows[2 * c2 + 0][g * 4 + t] = accx;
        rows[2 * c2 + 1][g * 4 + t] = accy;
    }
    __syncthreads();

    // ---- GEMM: out[node][tid] = sum_k rows[k][node] * W[k][tid] + b[tid] ----
    float bv = bias[tid];
    unsigned long long acc01 = pack2(bv, bv);
    unsigned long long acc23 = acc01, acc45 = acc01, acc67 = acc01;

    #pragma unroll 4
    for (int k = 0; k < D; k++) {
        float wv = W[k * D + tid];
        unsigned long long w2 = pack2(wv, wv);
        const ulonglong2* rp = (const ulonglong2*)&rows[k][0];
        ulonglong2 rA = rp[0];           // rows[k][0..3]  (LDS.128 broadcast)
        ulonglong2 rB = rp[1];           // rows[k][4..7]
        acc01 = fma2(rA.x, w2, acc01);
        acc23 = fma2(rA.y, w2, acc23);
        acc45 = fma2(rB.x, w2, acc45);
        acc67 = fma2(rB.y, w2, acc67);
    }

    float o[T];
    unpack2(acc01, o[0], o[1]);
    unpack2(acc23, o[2], o[3]);
    unpack2(acc45, o[4], o[5]);
    unpack2(acc67, o[6], o[7]);

    float csum = 0.f;
    #pragma unroll
    for (int t = 0; t < T; t++) {
        int node = base + t;
        if (node < n) {
            h_out[(size_t)node * D + tid] = o[t];
            csum += o[t];
        }
    }
    if (cs >= 0) atomicAdd(&g_colsum[cs * D + tid], csum);   // fused readout col-sum
}

// ---------------- final: readout MLP + match MLP + sigmoid ----------------
__global__ void k_match(const float* __restrict__ Wr,  const float* __restrict__ br,
                        const float* __restrict__ Wm1, const float* __restrict__ bm1,
                        const float* __restrict__ Wm2, const float* __restrict__ bm2,
                        float n_nodes, float* __restrict__ out)
{
    __shared__ float c[2 * D];
    __shared__ float red[D];
    int tid = threadIdx.x;          // 256 threads
    int g = tid / D;
    int j = tid % D;
    float invn = 1.0f / n_nodes;

    float acc = br[j];
    for (int k = 0; k < D; k++)
        acc += (g_colsum[g * D + k] * invn) * Wr[k * D + j];
    c[tid] = 1.0f / (1.0f + expf(-acc));    // g_p / g_s concatenated
    __syncthreads();

    if (tid < D) {
        float d1 = bm1[tid];
        for (int i = 0; i < 2 * D; i++)
            d1 += c[i] * Wm1[i * D + tid];
        red[tid] = d1 * Wm2[tid];
    }
    __syncthreads();

    if (tid == 0) {
        float s = 0.f;
        for (int i = 0; i < D; i++) s += red[i];
        out[0] = 1.0f / (1.0f + expf(-(s + bm2[0])));
    }
}

// ---------------- launch ----------------
extern "C" void kernel_launch(void* const* d_in, const int* in_sizes, int n_in,
                              void* d_out, int out_size)
{
    const float* feat_p = (const float*)d_in[0];
    const int*   src_p  = (const int*)d_in[1];
    const int*   dst_p  = (const int*)d_in[2];
    const float* feat_s = (const float*)d_in[3];
    const int*   src_s  = (const int*)d_in[4];
    const int*   dst_s  = (const int*)d_in[5];
    const float* W[3]   = { (const float*)d_in[6], (const float*)d_in[8], (const float*)d_in[10] };
    const float* b[3]   = { (const float*)d_in[7], (const float*)d_in[9], (const float*)d_in[11] };
    const float* Wr  = (const float*)d_in[12];
    const float* br  = (const float*)d_in[13];
    const float* Wm1 = (const float*)d_in[14];
    const float* bm1 = (const float*)d_in[15];
    const float* Wm2 = (const float*)d_in[16];
    const float* bm2 = (const float*)d_in[17];

    int n  = in_sizes[0] / D;
    int e0 = in_sizes[1];
    int e1 = in_sizes[4];
    int emax = e0 > e1 ? e0 : e1;

    dim3 gN((n + 511) / 512, 2);
    dim3 gE((emax + 511) / 512, 2);

    k_init<<<gN, 512>>>(n);
    k_count<<<gE, 512>>>(dst_p, dst_s, e0, e1);
    k_scan<<<2, 1024>>>(n);
    k_fill<<<gE, 512>>>(src_p, dst_p, src_s, dst_s, e0, e1);

    int nb = (n + T - 1) / T;
    // graphs sequential: keeps per-launch working set (~58 MB) L2-resident
    k_layer<<<nb, 128>>>(feat_p, 0, -1, 0, W[0], b[0], n, -1);
    k_layer<<<nb, 128>>>(feat_p, 0,  0, 1, W[1], b[1], n, -1);
    k_layer<<<nb, 128>>>(feat_p, 0,  1, 0, W[2], b[2], n,  0);
    k_layer<<<nb, 128>>>(feat_s, 1, -1, 0, W[0], b[0], n, -1);
    k_layer<<<nb, 128>>>(feat_s, 1,  0, 1, W[1], b[1], n, -1);
    k_layer<<<nb, 128>>>(feat_s, 1,  1, 0, W[2], b[2], n,  1);

    k_match<<<1, 256>>>(Wr, br, Wm1, bm1, Wm2, bm2, (float)n, (float*)d_out);
}

// round 6
// speedup vs baseline: 2.6790x; 1.0416x over previous
#include <cuda_runtime.h>
#include <cuda_bf16.h>
#include <math.h>

#define NMAX 50000
#define EMAX 1600000
#define D 128
#define H (D/2)
#define T 8
#define RP 12

__device__ __nv_bfloat162 g_bufh[2][2][NMAX * H];
__device__ int   g_deg[2][NMAX];
__device__ int   g_rowstart[2][NMAX + 1];
__device__ int   g_cursor[2][NMAX];
__device__ int   g_csr[2][EMAX];
__device__ float g_invdeg[2][NMAX];
__device__ float g_colsum[2 * D];

__device__ __forceinline__ unsigned long long pack2(float lo, float hi) {
    unsigned long long r;
    asm("mov.b64 %0, {%1, %2};" : "=l"(r) : "f"(lo), "f"(hi));
    return r;
}
__device__ __forceinline__ void unpack2(unsigned long long v, float& lo, float& hi) {
    asm("mov.b64 {%0, %1}, %2;" : "=f"(lo), "=f"(hi) : "l"(v));
}
__device__ __forceinline__ unsigned long long fma2(unsigned long long a,
                                                   unsigned long long b,
                                                   unsigned long long c) {
    unsigned long long d;
    asm("fma.rn.f32x2 %0, %1, %2, %3;" : "=l"(d) : "l"(a), "l"(b), "l"(c));
    return d;
}

__global__ void k_init(int n) {
    int gi = blockIdx.y;
    int i = blockIdx.x * blockDim.x + threadIdx.x;
    if (i < n) g_deg[gi][i] = 0;
    if (gi == 0 && blockIdx.x == 0 && threadIdx.x < 2 * D) g_colsum[threadIdx.x] = 0.f;
}

__global__ void k_count(const int* __restrict__ d0, const int* __restrict__ d1,
                        int e0, int e1) {
    int gi = blockIdx.y;
    const int* __restrict__ dst = gi ? d1 : d0;
    int e = gi ? e1 : e0;
    int i = blockIdx.x * blockDim.x + threadIdx.x;
    if (i < e) atomicAdd(&g_deg[gi][dst[i]], 1);
}

__global__ void k_scan(int n) {
    int gi = blockIdx.x;
    const int* __restrict__ deg = g_deg[gi];
    int* __restrict__ rowstart = g_rowstart[gi];
    int* __restrict__ cursor = g_cursor[gi];
    float* __restrict__ invdeg = g_invdeg[gi];

    __shared__ int s_warp[32];
    __shared__ int s_carry;
    int tid = threadIdx.x;
    int lane = tid & 31;
    int wid = tid >> 5;
    if (tid == 0) s_carry = 0;
    __syncthreads();

    for (int base = 0; base < n; base += 1024) {
        int i = base + tid;
        int v = (i < n) ? deg[i] : 0;
        int s = v;
        #pragma unroll
        for (int d = 1; d < 32; d <<= 1) {
            int t = __shfl_up_sync(0xffffffffu, s, d);
            if (lane >= d) s += t;
        }
        if (lane == 31) s_warp[wid] = s;
        __syncthreads();
        if (wid == 0) {
            int w = s_warp[lane];
            #pragma unroll
            for (int d = 1; d < 32; d <<= 1) {
                int t = __shfl_up_sync(0xffffffffu, w, d);
                if (lane >= d) w += t;
            }
            s_warp[lane] = w;
        }
        __syncthreads();
        int carry = s_carry;
        int excl = carry + (wid ? s_warp[wid - 1] : 0) + s - v;
        if (i < n) {
            rowstart[i] = excl;
            cursor[i]   = excl;
            invdeg[i]   = 1.0f / fmaxf((float)v, 1.0f);
        }
        __syncthreads();
        if (tid == 0) s_carry = carry + s_warp[31];
        __syncthreads();
    }
    if (tid == 0) rowstart[n] = s_carry;
}

__global__ void k_fill(const int* __restrict__ s0, const int* __restrict__ d0,
                       const int* __restrict__ s1, const int* __restrict__ d1,
                       int e0, int e1) {
    int gi = blockIdx.y;
    const int* __restrict__ src = gi ? s1 : s0;
    const int* __restrict__ dst = gi ? d1 : d0;
    int e = gi ? e1 : e0;
    int i = blockIdx.x * blockDim.x + threadIdx.x;
    if (i < e) {
        int p = atomicAdd(&g_cursor[gi][dst[i]], 1);
        g_csr[gi][p] = src[i];
    }
}

__global__ void k_feat2h(const float* __restrict__ f0, const float* __restrict__ f1, int n) {
    int gi = blockIdx.y;
    const float2* __restrict__ f = (const float2*)(gi ? f1 : f0);
    int i = blockIdx.x * blockDim.x + threadIdx.x;
    if (i < n * H) {
        float2 v = f[i];
        g_bufh[gi][0][i] = __floats2bfloat162_rn(v.x, v.y);
    }
}

// fused aggregate (mean, bf16x2 gathers) + GEMM + bias; both graphs via blockIdx.y.
// last_layer: skip h store, accumulate per-graph column sums instead.
__global__ void __launch_bounds__(128, 8) k_layer(
    int sel_in, int sel_out,
    const float* __restrict__ W, const float* __restrict__ bias, int n, int last_layer)
{
    int gi = blockIdx.y;
    const __nv_bfloat162* __restrict__ h_in = g_bufh[gi][sel_in];
    __nv_bfloat162* __restrict__ h_out = g_bufh[gi][sel_out];
    const int* __restrict__ rowstart = g_rowstart[gi];
    const int* __restrict__ csr = g_csr[gi];
    const float* __restrict__ invdeg = g_invdeg[gi];

    __shared__ float rows[D][RP];
    int tid = threadIdx.x;
    int c2  = tid & 63;
    int g   = tid >> 6;
    int base = blockIdx.x * T;

    #pragma unroll
    for (int t = 0; t < 4; t++) {
        int node = base + g * 4 + t;
        float accx = 0.f, accy = 0.f;
        if (node < n) {
            int s = rowstart[node];
            int e = rowstart[node + 1];
            float a0x = 0.f, a0y = 0.f, a1x = 0.f, a1y = 0.f;
            float a2x = 0.f, a2y = 0.f, a3x = 0.f, a3y = 0.f;
            int i = s;
            for (; i + 4 <= e; i += 4) {
                int c0 = csr[i], c1 = csr[i + 1], cc = csr[i + 2], c3 = csr[i + 3];
                unsigned u0 = __ldcg((const unsigned*)&h_in[(size_t)c0 * H + c2]);
                unsigned u1 = __ldcg((const unsigned*)&h_in[(size_t)c1 * H + c2]);
                unsigned u2 = __ldcg((const unsigned*)&h_in[(size_t)cc * H + c2]);
                unsigned u3 = __ldcg((const unsigned*)&h_in[(size_t)c3 * H + c2]);
                float2 v0 = __bfloat1622float2(*reinterpret_cast<__nv_bfloat162*>(&u0));
                float2 v1 = __bfloat1622float2(*reinterpret_cast<__nv_bfloat162*>(&u1));
                float2 v2 = __bfloat1622float2(*reinterpret_cast<__nv_bfloat162*>(&u2));
                float2 v3 = __bfloat1622float2(*reinterpret_cast<__nv_bfloat162*>(&u3));
                a0x += v0.x; a0y += v0.y;
                a1x += v1.x; a1y += v1.y;
                a2x += v2.x; a2y += v2.y;
                a3x += v3.x; a3y += v3.y;
            }
            for (; i < e; i++) {
                unsigned u = __ldcg((const unsigned*)&h_in[(size_t)csr[i] * H + c2]);
                float2 v = __bfloat1622float2(*reinterpret_cast<__nv_bfloat162*>(&u));
                a0x += v.x; a0y += v.y;
            }
            float id = invdeg[node];
            accx = ((a0x + a1x) + (a2x + a3x)) * id;
            accy = ((a0y + a1y) + (a2y + a3y)) * id;
        }
        rows[2 * c2 + 0][g * 4 + t] = accx;
        rows[2 * c2 + 1][g * 4 + t] = accy;
    }
    __syncthreads();

    float bv = bias[tid];
    unsigned long long acc01 = pack2(bv, bv);
    unsigned long long acc23 = acc01, acc45 = acc01, acc67 = acc01;

    #pragma unroll 4
    for (int k = 0; k < D; k++) {
        float wv = W[k * D + tid];
        unsigned long long w2 = pack2(wv, wv);
        const ulonglong2* rp = (const ulonglong2*)&rows[k][0];
        ulonglong2 rA = rp[0];
        ulonglong2 rB = rp[1];
        acc01 = fma2(rA.x, w2, acc01);
        acc23 = fma2(rA.y, w2, acc23);
        acc45 = fma2(rB.x, w2, acc45);
        acc67 = fma2(rB.y, w2, acc67);
    }

    float o[T];
    unpack2(acc01, o[0], o[1]);
    unpack2(acc23, o[2], o[3]);
    unpack2(acc45, o[4], o[5]);
    unpack2(acc67, o[6], o[7]);

    if (last_layer) {
        float csum = 0.f;
        #pragma unroll
        for (int t = 0; t < T; t++)
            if (base + t < n) csum += o[t];
        atomicAdd(&g_colsum[gi * D + tid], csum);
    } else {
        #pragma unroll
        for (int t = 0; t < T; t++) {
            float hi = __shfl_xor_sync(0xffffffffu, o[t], 1);
            int node = base + t;
            if (!(tid & 1) && node < n)
                h_out[(size_t)node * H + (tid >> 1)] = __floats2bfloat162_rn(o[t], hi);
        }
    }
}

__global__ void k_match(const float* __restrict__ Wr,  const float* __restrict__ br,
                        const float* __restrict__ Wm1, const float* __restrict__ bm1,
                        const float* __restrict__ Wm2, const float* __restrict__ bm2,
                        float n_nodes, float* __restrict__ out)
{
    __shared__ float c[2 * D];
    __shared__ float red[D];
    int tid = threadIdx.x;
    int g = tid / D;
    int j = tid % D;
    float invn = 1.0f / n_nodes;

    float acc = br[j];
    for (int k = 0; k < D; k++)
        acc += (g_colsum[g * D + k] * invn) * Wr[k * D + j];
    c[tid] = 1.0f / (1.0f + expf(-acc));
    __syncthreads();

    if (tid < D) {
        float d1 = bm1[tid];
        for (int i = 0; i < 2 * D; i++)
            d1 += c[i] * Wm1[i * D + tid];
        red[tid] = d1 * Wm2[tid];
    }
    __syncthreads();

    if (tid == 0) {
        float s = 0.f;
        for (int i = 0; i < D; i++) s += red[i];
        out[0] = 1.0f / (1.0f + expf(-(s + bm2[0])));
    }
}

extern "C" void kernel_launch(void* const* d_in, const int* in_sizes, int n_in,
                              void* d_out, int out_size)
{
    const float* feat_p = (const float*)d_in[0];
    const int*   src_p  = (const int*)d_in[1];
    const int*   dst_p  = (const int*)d_in[2];
    const float* feat_s = (const float*)d_in[3];
    const int*   src_s  = (const int*)d_in[4];
    const int*   dst_s  = (const int*)d_in[5];
    const float* W[3]   = { (const float*)d_in[6], (const float*)d_in[8], (const float*)d_in[10] };
    const float* b[3]   = { (const float*)d_in[7], (const float*)d_in[9], (const float*)d_in[11] };
    const float* Wr  = (const float*)d_in[12];
    const float* br  = (const float*)d_in[13];
    const float* Wm1 = (const float*)d_in[14];
    const float* bm1 = (const float*)d_in[15];
    const float* Wm2 = (const float*)d_in[16];
    const float* bm2 = (const float*)d_in[17];

    int n  = in_sizes[0] / D;
    int e0 = in_sizes[1];
    int e1 = in_sizes[4];
    int emax = e0 > e1 ? e0 : e1;

    dim3 gN((n + 511) / 512, 2);
    dim3 gE((emax + 511) / 512, 2);
    dim3 gF((n * H + 255) / 256, 2);

    k_init<<<gN, 512>>>(n);
    k_count<<<gE, 512>>>(dst_p, dst_s, e0, e1);
    k_scan<<<2, 1024>>>(n);
    k_fill<<<gE, 512>>>(src_p, dst_p, src_s, dst_s, e0, e1);
    k_feat2h<<<gF, 256>>>(feat_p, feat_s, n);

    dim3 gL((n + T - 1) / T, 2);
    k_layer<<<gL, 128>>>(0, 1, W[0], b[0], n, 0);   // feat(bf16) -> buf1
    k_layer<<<gL, 128>>>(1, 0, W[1], b[1], n, 0);   // buf1 -> buf0
    k_layer<<<gL, 128>>>(0, 1, W[2], b[2], n, 1);   // buf0 -> colsum only

    k_match<<<1, 256>>>(Wr, br, Wm1, bm1, Wm2, bm2, (float)n, (float*)d_out);
}

// round 7
// speedup vs baseline: 2.9876x; 1.1152x over previous
#include <cuda_runtime.h>
#include <cuda_bf16.h>
#include <math.h>

#define NMAX 50000
#define EMAX 1600000
#define D 128
#define H (D/2)
#define T 8
#define RP 12

__device__ __nv_bfloat162 g_bufh[2][2][NMAX * H];
__device__ int   g_deg[2][NMAX];
__device__ int   g_rowstart[2][NMAX + 1];
__device__ int   g_cursor[2][NMAX];
__device__ int   g_csr[2][EMAX];
__device__ float g_invdeg[2][NMAX];
__device__ float g_colsum[2 * D];

__device__ __forceinline__ unsigned long long pack2(float lo, float hi) {
    unsigned long long r;
    asm("mov.b64 %0, {%1, %2};" : "=l"(r) : "f"(lo), "f"(hi));
    return r;
}
__device__ __forceinline__ void unpack2(unsigned long long v, float& lo, float& hi) {
    asm("mov.b64 {%0, %1}, %2;" : "=f"(lo), "=f"(hi) : "l"(v));
}
__device__ __forceinline__ unsigned long long fma2(unsigned long long a,
                                                   unsigned long long b,
                                                   unsigned long long c) {
    unsigned long long d;
    asm("fma.rn.f32x2 %0, %1, %2, %3;" : "=l"(d) : "l"(a), "l"(b), "l"(c));
    return d;
}

__global__ void k_init(int n) {
    int gi = blockIdx.y;
    int i = blockIdx.x * blockDim.x + threadIdx.x;
    if (i < n) g_deg[gi][i] = 0;
    if (gi == 0 && blockIdx.x == 0 && threadIdx.x < 2 * D) g_colsum[threadIdx.x] = 0.f;
}

__global__ void k_count(const int* __restrict__ d0, const int* __restrict__ d1,
                        int e0, int e1) {
    int gi = blockIdx.y;
    const int* __restrict__ dst = gi ? d1 : d0;
    int e = gi ? e1 : e0;
    int i = blockIdx.x * blockDim.x + threadIdx.x;
    if (i < e) atomicAdd(&g_deg[gi][dst[i]], 1);
}

__global__ void k_scan(int n) {
    int gi = blockIdx.x;
    const int* __restrict__ deg = g_deg[gi];
    int* __restrict__ rowstart = g_rowstart[gi];
    int* __restrict__ cursor = g_cursor[gi];
    float* __restrict__ invdeg = g_invdeg[gi];

    __shared__ int s_warp[32];
    __shared__ int s_carry;
    int tid = threadIdx.x;
    int lane = tid & 31;
    int wid = tid >> 5;
    if (tid == 0) s_carry = 0;
    __syncthreads();

    for (int base = 0; base < n; base += 1024) {
        int i = base + tid;
        int v = (i < n) ? deg[i] : 0;
        int s = v;
        #pragma unroll
        for (int d = 1; d < 32; d <<= 1) {
            int t = __shfl_up_sync(0xffffffffu, s, d);
            if (lane >= d) s += t;
        }
        if (lane == 31) s_warp[wid] = s;
        __syncthreads();
        if (wid == 0) {
            int w = s_warp[lane];
            #pragma unroll
            for (int d = 1; d < 32; d <<= 1) {
                int t = __shfl_up_sync(0xffffffffu, w, d);
                if (lane >= d) w += t;
            }
            s_warp[lane] = w;
        }
        __syncthreads();
        int carry = s_carry;
        int excl = carry + (wid ? s_warp[wid - 1] : 0) + s - v;
        if (i < n) {
            rowstart[i] = excl;
            cursor[i]   = excl;
            invdeg[i]   = 1.0f / fmaxf((float)v, 1.0f);
        }
        __syncthreads();
        if (tid == 0) s_carry = carry + s_warp[31];
        __syncthreads();
    }
    if (tid == 0) rowstart[n] = s_carry;
}

__global__ void k_fill(const int* __restrict__ s0, const int* __restrict__ d0,
                       const int* __restrict__ s1, const int* __restrict__ d1,
                       int e0, int e1) {
    int gi = blockIdx.y;
    const int* __restrict__ src = gi ? s1 : s0;
    const int* __restrict__ dst = gi ? d1 : d0;
    int e = gi ? e1 : e0;
    int i = blockIdx.x * blockDim.x + threadIdx.x;
    if (i < e) {
        int p = atomicAdd(&g_cursor[gi][dst[i]], 1);
        g_csr[gi][p] = src[i];
    }
}

__global__ void k_feat2h(const float* __restrict__ f0, const float* __restrict__ f1, int n) {
    int gi = blockIdx.y;
    const float2* __restrict__ f = (const float2*)(gi ? f1 : f0);
    int i = blockIdx.x * blockDim.x + threadIdx.x;
    if (i < n * H) {
        float2 v = f[i];
        g_bufh[gi][0][i] = __floats2bfloat162_rn(v.x, v.y);
    }
}

// fused aggregate (mean, bf16x2 gathers, MLP=8) + GEMM + bias; graphs via blockIdx.y.
// last_layer: skip h store, accumulate per-graph column sums instead.
__global__ void __launch_bounds__(128, 12) k_layer(
    int sel_in, int sel_out,
    const float* __restrict__ W, const float* __restrict__ bias, int n, int last_layer)
{
    int gi = blockIdx.y;
    const __nv_bfloat162* __restrict__ h_in = g_bufh[gi][sel_in];
    __nv_bfloat162* __restrict__ h_out = g_bufh[gi][sel_out];
    const int* __restrict__ rowstart = g_rowstart[gi];
    const int* __restrict__ csr = g_csr[gi];
    const float* __restrict__ invdeg = g_invdeg[gi];

    __shared__ float rows[D][RP];
    int tid = threadIdx.x;
    int c2  = tid & 63;
    int g   = tid >> 6;
    int base = blockIdx.x * T;

    #pragma unroll
    for (int t = 0; t < 4; t++) {
        int node = base + g * 4 + t;
        float accx = 0.f, accy = 0.f;
        if (node < n) {
            int s = rowstart[node];
            int e = rowstart[node + 1];
            float a0x = 0.f, a0y = 0.f, a1x = 0.f, a1y = 0.f;
            float a2x = 0.f, a2y = 0.f, a3x = 0.f, a3y = 0.f;
            int i = s;
            // unroll 8: issue 8 independent gathers before any consumption (MLP=8)
            for (; i + 8 <= e; i += 8) {
                int c0 = csr[i],     c1 = csr[i + 1], cA = csr[i + 2], c3 = csr[i + 3];
                int c4 = csr[i + 4], c5 = csr[i + 5], c6 = csr[i + 6], c7 = csr[i + 7];
                unsigned u0 = __ldcg((const unsigned*)&h_in[(size_t)c0 * H + c2]);
                unsigned u1 = __ldcg((const unsigned*)&h_in[(size_t)c1 * H + c2]);
                unsigned u2 = __ldcg((const unsigned*)&h_in[(size_t)cA * H + c2]);
                unsigned u3 = __ldcg((const unsigned*)&h_in[(size_t)c3 * H + c2]);
                unsigned u4 = __ldcg((const unsigned*)&h_in[(size_t)c4 * H + c2]);
                unsigned u5 = __ldcg((const unsigned*)&h_in[(size_t)c5 * H + c2]);
                unsigned u6 = __ldcg((const unsigned*)&h_in[(size_t)c6 * H + c2]);
                unsigned u7 = __ldcg((const unsigned*)&h_in[(size_t)c7 * H + c2]);
                float2 v0 = __bfloat1622float2(*reinterpret_cast<__nv_bfloat162*>(&u0));
                float2 v1 = __bfloat1622float2(*reinterpret_cast<__nv_bfloat162*>(&u1));
                float2 v2 = __bfloat1622float2(*reinterpret_cast<__nv_bfloat162*>(&u2));
                float2 v3 = __bfloat1622float2(*reinterpret_cast<__nv_bfloat162*>(&u3));
                float2 v4 = __bfloat1622float2(*reinterpret_cast<__nv_bfloat162*>(&u4));
                float2 v5 = __bfloat1622float2(*reinterpret_cast<__nv_bfloat162*>(&u5));
                float2 v6 = __bfloat1622float2(*reinterpret_cast<__nv_bfloat162*>(&u6));
                float2 v7 = __bfloat1622float2(*reinterpret_cast<__nv_bfloat162*>(&u7));
                a0x += v0.x; a0y += v0.y;
                a1x += v1.x; a1y += v1.y;
                a2x += v2.x; a2y += v2.y;
                a3x += v3.x; a3y += v3.y;
                a0x += v4.x; a0y += v4.y;
                a1x += v5.x; a1y += v5.y;
                a2x += v6.x; a2y += v6.y;
                a3x += v7.x; a3y += v7.y;
            }
            for (; i < e; i++) {
                unsigned u = __ldcg((const unsigned*)&h_in[(size_t)csr[i] * H + c2]);
                float2 v = __bfloat1622float2(*reinterpret_cast<__nv_bfloat162*>(&u));
                a0x += v.x; a0y += v.y;
            }
            float id = invdeg[node];
            accx = ((a0x + a1x) + (a2x + a3x)) * id;
            accy = ((a0y + a1y) + (a2y + a3y)) * id;
        }
        rows[2 * c2 + 0][g * 4 + t] = accx;
        rows[2 * c2 + 1][g * 4 + t] = accy;
    }
    __syncthreads();

    float bv = bias[tid];
    unsigned long long acc01 = pack2(bv, bv);
    unsigned long long acc23 = acc01, acc45 = acc01, acc67 = acc01;

    #pragma unroll 4
    for (int k = 0; k < D; k++) {
        float wv = W[k * D + tid];
        unsigned long long w2 = pack2(wv, wv);
        const ulonglong2* rp = (const ulonglong2*)&rows[k][0];
        ulonglong2 rA = rp[0];
        ulonglong2 rB = rp[1];
        acc01 = fma2(rA.x, w2, acc01);
        acc23 = fma2(rA.y, w2, acc23);
        acc45 = fma2(rB.x, w2, acc45);
        acc67 = fma2(rB.y, w2, acc67);
    }

    float o[T];
    unpack2(acc01, o[0], o[1]);
    unpack2(acc23, o[2], o[3]);
    unpack2(acc45, o[4], o[5]);
    unpack2(acc67, o[6], o[7]);

    if (last_layer) {
        float csum = 0.f;
        #pragma unroll
        for (int t = 0; t < T; t++)
            if (base + t < n) csum += o[t];
        atomicAdd(&g_colsum[gi * D + tid], csum);
    } else {
        #pragma unroll
        for (int t = 0; t < T; t++) {
            float hi = __shfl_xor_sync(0xffffffffu, o[t], 1);
            int node = base + t;
            if (!(tid & 1) && node < n)
                h_out[(size_t)node * H + (tid >> 1)] = __floats2bfloat162_rn(o[t], hi);
        }
    }
}

__global__ void k_match(const float* __restrict__ Wr,  const float* __restrict__ br,
                        const float* __restrict__ Wm1, const float* __restrict__ bm1,
                        const float* __restrict__ Wm2, const float* __restrict__ bm2,
                        float n_nodes, float* __restrict__ out)
{
    __shared__ float c[2 * D];
    __shared__ float red[D];
    int tid = threadIdx.x;
    int g = tid / D;
    int j = tid % D;
    float invn = 1.0f / n_nodes;

    float acc = br[j];
    for (int k = 0; k < D; k++)
        acc += (g_colsum[g * D + k] * invn) * Wr[k * D + j];
    c[tid] = 1.0f / (1.0f + expf(-acc));
    __syncthreads();

    if (tid < D) {
        float d1 = bm1[tid];
        for (int i = 0; i < 2 * D; i++)
            d1 += c[i] * Wm1[i * D + tid];
        red[tid] = d1 * Wm2[tid];
    }
    __syncthreads();

    if (tid == 0) {
        float s = 0.f;
        for (int i = 0; i < D; i++) s += red[i];
        out[0] = 1.0f / (1.0f + expf(-(s + bm2[0])));
    }
}

extern "C" void kernel_launch(void* const* d_in, const int* in_sizes, int n_in,
                              void* d_out, int out_size)
{
    const float* feat_p = (const float*)d_in[0];
    const int*   src_p  = (const int*)d_in[1];
    const int*   dst_p  = (const int*)d_in[2];
    const float* feat_s = (const float*)d_in[3];
    const int*   src_s  = (const int*)d_in[4];
    const int*   dst_s  = (const int*)d_in[5];
    const float* W[3]   = { (const float*)d_in[6], (const float*)d_in[8], (const float*)d_in[10] };
    const float* b[3]   = { (const float*)d_in[7], (const float*)d_in[9], (const float*)d_in[11] };
    const float* Wr  = (const float*)d_in[12];
    const float* br  = (const float*)d_in[13];
    const float* Wm1 = (const float*)d_in[14];
    const float* bm1 = (const float*)d_in[15];
    const float* Wm2 = (const float*)d_in[16];
    const float* bm2 = (const float*)d_in[17];

    int n  = in_sizes[0] / D;
    int e0 = in_sizes[1];
    int e1 = in_sizes[4];
    int emax = e0 > e1 ? e0 : e1;

    dim3 gN((n + 511) / 512, 2);
    dim3 gE((emax + 511) / 512, 2);
    dim3 gF((n * H + 255) / 256, 2);

    k_init<<<gN, 512>>>(n);
    k_count<<<gE, 512>>>(dst_p, dst_s, e0, e1);
    k_scan<<<2, 1024>>>(n);
    k_fill<<<gE, 512>>>(src_p, dst_p, src_s, dst_s, e0, e1);
    k_feat2h<<<gF, 256>>>(feat_p, feat_s, n);

    dim3 gL((n + T - 1) / T, 2);
    k_layer<<<gL, 128>>>(0, 1, W[0], b[0], n, 0);   // feat(bf16) -> buf1
    k_layer<<<gL, 128>>>(1, 0, W[1], b[1], n, 0);   // buf1 -> buf0
    k_layer<<<gL, 128>>>(0, 1, W[2], b[2], n, 1);   // buf0 -> colsum only

    k_match<<<1, 256>>>(Wr, br, Wm1, bm1, Wm2, bm2, (float)n, (float*)d_out);
}

// round 8
// speedup vs baseline: 3.1406x; 1.0512x over previous
#include <cuda_runtime.h>
#include <cuda_bf16.h>
#include <math.h>

#define NMAX 50000
#define EMAX 1600000
#define D 128
#define H (D/2)
#define T 8
#define RP 12

__device__ __nv_bfloat162 g_bufh[2][2][NMAX * H];
__device__ int   g_deg[2][NMAX];
__device__ int   g_rowstart[2][NMAX + 1];
__device__ int   g_cursor[2][NMAX];
__device__ int   g_csr[2][EMAX];
__device__ float g_invdeg[2][NMAX];
__device__ float g_colsum[2 * D];

__device__ __forceinline__ unsigned long long pack2(float lo, float hi) {
    unsigned long long r;
    asm("mov.b64 %0, {%1, %2};" : "=l"(r) : "f"(lo), "f"(hi));
    return r;
}
__device__ __forceinline__ void unpack2(unsigned long long v, float& lo, float& hi) {
    asm("mov.b64 {%0, %1}, %2;" : "=f"(lo), "=f"(hi) : "l"(v));
}
__device__ __forceinline__ unsigned long long fma2(unsigned long long a,
                                                   unsigned long long b,
                                                   unsigned long long c) {
    unsigned long long d;
    asm("fma.rn.f32x2 %0, %1, %2, %3;" : "=l"(d) : "l"(a), "l"(b), "l"(c));
    return d;
}
// expand packed bf16x2 (u32) into packed f32x2 (u64) with shifts/masks (no cvt)
__device__ __forceinline__ unsigned long long bfpair(unsigned u) {
    float lo = __int_as_float(u << 16);
    float hi = __int_as_float(u & 0xffff0000u);
    return pack2(lo, hi);
}

__global__ void k_init(int n) {
    int gi = blockIdx.y;
    int i = blockIdx.x * blockDim.x + threadIdx.x;
    if (i < n) g_deg[gi][i] = 0;
    if (gi == 0 && blockIdx.x == 0 && threadIdx.x < 2 * D) g_colsum[threadIdx.x] = 0.f;
}

__global__ void k_count(const int* __restrict__ d0, const int* __restrict__ d1,
                        int e0, int e1) {
    int gi = blockIdx.y;
    const int* __restrict__ dst = gi ? d1 : d0;
    int e = gi ? e1 : e0;
    int i = blockIdx.x * blockDim.x + threadIdx.x;
    if (i < e) atomicAdd(&g_deg[gi][dst[i]], 1);
}

__global__ void k_scan(int n) {
    int gi = blockIdx.x;
    const int* __restrict__ deg = g_deg[gi];
    int* __restrict__ rowstart = g_rowstart[gi];
    int* __restrict__ cursor = g_cursor[gi];
    float* __restrict__ invdeg = g_invdeg[gi];

    __shared__ int s_warp[32];
    __shared__ int s_carry;
    int tid = threadIdx.x;
    int lane = tid & 31;
    int wid = tid >> 5;
    if (tid == 0) s_carry = 0;
    __syncthreads();

    for (int base = 0; base < n; base += 1024) {
        int i = base + tid;
        int v = (i < n) ? deg[i] : 0;
        int s = v;
        #pragma unroll
        for (int d = 1; d < 32; d <<= 1) {
            int t = __shfl_up_sync(0xffffffffu, s, d);
            if (lane >= d) s += t;
        }
        if (lane == 31) s_warp[wid] = s;
        __syncthreads();
        if (wid == 0) {
            int w = s_warp[lane];
            #pragma unroll
            for (int d = 1; d < 32; d <<= 1) {
                int t = __shfl_up_sync(0xffffffffu, w, d);
                if (lane >= d) w += t;
            }
            s_warp[lane] = w;
        }
        __syncthreads();
        int carry = s_carry;
        int excl = carry + (wid ? s_warp[wid - 1] : 0) + s - v;
        if (i < n) {
            rowstart[i] = excl;
            cursor[i]   = excl;
            invdeg[i]   = 1.0f / fmaxf((float)v, 1.0f);
        }
        __syncthreads();
        if (tid == 0) s_carry = carry + s_warp[31];
        __syncthreads();
    }
    if (tid == 0) rowstart[n] = s_carry;
}

__global__ void k_fill(const int* __restrict__ s0, const int* __restrict__ d0,
                       const int* __restrict__ s1, const int* __restrict__ d1,
                       int e0, int e1) {
    int gi = blockIdx.y;
    const int* __restrict__ src = gi ? s1 : s0;
    const int* __restrict__ dst = gi ? d1 : d0;
    int e = gi ? e1 : e0;
    int i = blockIdx.x * blockDim.x + threadIdx.x;
    if (i < e) {
        int p = atomicAdd(&g_cursor[gi][dst[i]], 1);
        g_csr[gi][p] = src[i];
    }
}

__global__ void k_feat2h(const float* __restrict__ f0, const float* __restrict__ f1, int n) {
    int gi = blockIdx.y;
    const float2* __restrict__ f = (const float2*)(gi ? f1 : f0);
    int i = blockIdx.x * blockDim.x + threadIdx.x;
    if (i < n * H) {
        float2 v = f[i];
        g_bufh[gi][0][i] = __floats2bfloat162_rn(v.x, v.y);
    }
}

// fused aggregate (mean, LDG.64 bf16 gathers, packed f32x2 adds) + GEMM + bias.
// 128 threads: c4 = tid&31 covers cols [4c4, 4c4+4); g = tid>>5 handles nodes {2g, 2g+1}.
// last_layer: skip h store, accumulate per-graph column sums instead.
__global__ void __launch_bounds__(128, 12) k_layer(
    int sel_in, int sel_out,
    const float* __restrict__ W, const float* __restrict__ bias, int n, int last_layer)
{
    int gi = blockIdx.y;
    const __nv_bfloat162* __restrict__ h_in = g_bufh[gi][sel_in];
    __nv_bfloat162* __restrict__ h_out = g_bufh[gi][sel_out];
    const int* __restrict__ rowstart = g_rowstart[gi];
    const int* __restrict__ csr = g_csr[gi];
    const float* __restrict__ invdeg = g_invdeg[gi];

    __shared__ float rows[D][RP];
    int tid = threadIdx.x;
    int c4  = tid & 31;             // covers packed cols {2c4, 2c4+1} = floats [4c4,4c4+4)
    int g   = tid >> 5;             // node pair: base + 2g, base + 2g + 1
    int base = blockIdx.x * T;
    const unsigned long long one2 = pack2(1.0f, 1.0f);

    #pragma unroll
    for (int t = 0; t < 2; t++) {
        int node = base + 2 * g + t;
        float r0 = 0.f, r1 = 0.f, r2 = 0.f, r3 = 0.f;
        if (node < n) {
            int s = rowstart[node];
            int e = rowstart[node + 1];
            unsigned long long aA0 = 0, aB0 = 0, aA1 = 0, aB1 = 0;  // packed f32x2 accs (0.0 bits)
            int i = s;
            for (; i + 4 <= e; i += 4) {
                int c0 = csr[i], c1 = csr[i + 1], cA = csr[i + 2], c3 = csr[i + 3];
                uint2 u0 = __ldcg((const uint2*)&h_in[(size_t)c0 * H + 2 * c4]);
                uint2 u1 = __ldcg((const uint2*)&h_in[(size_t)c1 * H + 2 * c4]);
                uint2 u2 = __ldcg((const uint2*)&h_in[(size_t)cA * H + 2 * c4]);
                uint2 u3 = __ldcg((const uint2*)&h_in[(size_t)c3 * H + 2 * c4]);
                aA0 = fma2(bfpair(u0.x), one2, aA0);
                aB0 = fma2(bfpair(u0.y), one2, aB0);
                aA1 = fma2(bfpair(u1.x), one2, aA1);
                aB1 = fma2(bfpair(u1.y), one2, aB1);
                aA0 = fma2(bfpair(u2.x), one2, aA0);
                aB0 = fma2(bfpair(u2.y), one2, aB0);
                aA1 = fma2(bfpair(u3.x), one2, aA1);
                aB1 = fma2(bfpair(u3.y), one2, aB1);
            }
            for (; i < e; i++) {
                uint2 u = __ldcg((const uint2*)&h_in[(size_t)csr[i] * H + 2 * c4]);
                aA0 = fma2(bfpair(u.x), one2, aA0);
                aB0 = fma2(bfpair(u.y), one2, aB0);
            }
            float x0, x1, y0, y1, x2, x3, y2, y3;
            unpack2(aA0, x0, x1);
            unpack2(aA1, x2, x3);
            unpack2(aB0, y0, y1);
            unpack2(aB1, y2, y3);
            float id = invdeg[node];
            r0 = (x0 + x2) * id;
            r1 = (x1 + x3) * id;
            r2 = (y0 + y2) * id;
            r3 = (y1 + y3) * id;
        }
        int tt = 2 * g + t;
        rows[4 * c4 + 0][tt] = r0;
        rows[4 * c4 + 1][tt] = r1;
        rows[4 * c4 + 2][tt] = r2;
        rows[4 * c4 + 3][tt] = r3;
    }
    __syncthreads();

    float bv = bias[tid];
    unsigned long long acc01 = pack2(bv, bv);
    unsigned long long acc23 = acc01, acc45 = acc01, acc67 = acc01;

    #pragma unroll 4
    for (int k = 0; k < D; k++) {
        float wv = W[k * D + tid];
        unsigned long long w2 = pack2(wv, wv);
        const ulonglong2* rp = (const ulonglong2*)&rows[k][0];
        ulonglong2 rA = rp[0];
        ulonglong2 rB = rp[1];
        acc01 = fma2(rA.x, w2, acc01);
        acc23 = fma2(rA.y, w2, acc23);
        acc45 = fma2(rB.x, w2, acc45);
        acc67 = fma2(rB.y, w2, acc67);
    }

    float o[T];
    unpack2(acc01, o[0], o[1]);
    unpack2(acc23, o[2], o[3]);
    unpack2(acc45, o[4], o[5]);
    unpack2(acc67, o[6], o[7]);

    if (last_layer) {
        float csum = 0.f;
        #pragma unroll
        for (int t = 0; t < T; t++)
            if (base + t < n) csum += o[t];
        atomicAdd(&g_colsum[gi * D + tid], csum);
    } else {
        #pragma unroll
        for (int t = 0; t < T; t++) {
            float hi = __shfl_xor_sync(0xffffffffu, o[t], 1);
            int node = base + t;
            if (!(tid & 1) && node < n)
                h_out[(size_t)node * H + (tid >> 1)] = __floats2bfloat162_rn(o[t], hi);
        }
    }
}

__global__ void k_match(const float* __restrict__ Wr,  const float* __restrict__ br,
                        const float* __restrict__ Wm1, const float* __restrict__ bm1,
                        const float* __restrict__ Wm2, const float* __restrict__ bm2,
                        float n_nodes, float* __restrict__ out)
{
    __shared__ float c[2 * D];
    __shared__ float red[D];
    int tid = threadIdx.x;
    int g = tid / D;
    int j = tid % D;
    float invn = 1.0f / n_nodes;

    float acc = br[j];
    for (int k = 0; k < D; k++)
        acc += (g_colsum[g * D + k] * invn) * Wr[k * D + j];
    c[tid] = 1.0f / (1.0f + expf(-acc));
    __syncthreads();

    if (tid < D) {
        float d1 = bm1[tid];
        for (int i = 0; i < 2 * D; i++)
            d1 += c[i] * Wm1[i * D + tid];
        red[tid] = d1 * Wm2[tid];
    }
    __syncthreads();

    if (tid == 0) {
        float s = 0.f;
        for (int i = 0; i < D; i++) s += red[i];
        out[0] = 1.0f / (1.0f + expf(-(s + bm2[0])));
    }
}

extern "C" void kernel_launch(void* const* d_in, const int* in_sizes, int n_in,
                              void* d_out, int out_size)
{
    const float* feat_p = (const float*)d_in[0];
    const int*   src_p  = (const int*)d_in[1];
    const int*   dst_p  = (const int*)d_in[2];
    const float* feat_s = (const float*)d_in[3];
    const int*   src_s  = (const int*)d_in[4];
    const int*   dst_s  = (const int*)d_in[5];
    const float* W[3]   = { (const float*)d_in[6], (const float*)d_in[8], (const float*)d_in[10] };
    const float* b[3]   = { (const float*)d_in[7], (const float*)d_in[9], (const float*)d_in[11] };
    const float* Wr  = (const float*)d_in[12];
    const float* br  = (const float*)d_in[13];
    const float* Wm1 = (const float*)d_in[14];
    const float* bm1 = (const float*)d_in[15];
    const float* Wm2 = (const float*)d_in[16];
    const float* bm2 = (const float*)d_in[17];

    int n  = in_sizes[0] / D;
    int e0 = in_sizes[1];
    int e1 = in_sizes[4];
    int emax = e0 > e1 ? e0 : e1;

    dim3 gN((n + 511) / 512, 2);
    dim3 gE((emax + 511) / 512, 2);
    dim3 gF((n * H + 255) / 256, 2);

    k_init<<<gN, 512>>>(n);
    k_count<<<gE, 512>>>(dst_p, dst_s, e0, e1);
    k_scan<<<2, 1024>>>(n);
    k_fill<<<gE, 512>>>(src_p, dst_p, src_s, dst_s, e0, e1);
    k_feat2h<<<gF, 256>>>(feat_p, feat_s, n);

    dim3 gL((n + T - 1) / T, 2);
    k_layer<<<gL, 128>>>(0, 1, W[0], b[0], n, 0);   // feat(bf16) -> buf1
    k_layer<<<gL, 128>>>(1, 0, W[1], b[1], n, 0);   // buf1 -> buf0
    k_layer<<<gL, 128>>>(0, 1, W[2], b[2], n, 1);   // buf0 -> colsum only

    k_match<<<1, 256>>>(Wr, br, Wm1, bm1, Wm2, bm2, (float)n, (float*)d_out);
}

// round 9
// speedup vs baseline: 3.1694x; 1.0092x over previous
#include <cuda_runtime.h>
#include <cuda_bf16.h>
#include <math.h>

#define NMAX 50000
#define EMAX 1600000
#define D 128
#define H (D/2)
#define T 16
#define RP 20   // 80B smem row stride: 16B-aligned ulonglong2 loads at offsets 0/4/8/12

__device__ __nv_bfloat162 g_bufh[2][2][NMAX * H];
__device__ int   g_deg[2][NMAX];
__device__ int   g_rowstart[2][NMAX + 1];
__device__ int   g_cursor[2][NMAX];
__device__ int   g_csr[2][EMAX];
__device__ float g_invdeg[2][NMAX];
__device__ float g_colsum[2 * D];

__device__ __forceinline__ unsigned long long pack2(float lo, float hi) {
    unsigned long long r;
    asm("mov.b64 %0, {%1, %2};" : "=l"(r) : "f"(lo), "f"(hi));
    return r;
}
__device__ __forceinline__ void unpack2(unsigned long long v, float& lo, float& hi) {
    asm("mov.b64 {%0, %1}, %2;" : "=f"(lo), "=f"(hi) : "l"(v));
}
__device__ __forceinline__ unsigned long long fma2(unsigned long long a,
                                                   unsigned long long b,
                                                   unsigned long long c) {
    unsigned long long d;
    asm("fma.rn.f32x2 %0, %1, %2, %3;" : "=l"(d) : "l"(a), "l"(b), "l"(c));
    return d;
}
// expand packed bf16x2 (u32) into packed f32x2 (u64) with shifts/masks (no cvt)
__device__ __forceinline__ unsigned long long bfpair(unsigned u) {
    float lo = __int_as_float(u << 16);
    float hi = __int_as_float(u & 0xffff0000u);
    return pack2(lo, hi);
}

__global__ void k_init(int n) {
    int gi = blockIdx.y;
    int i = blockIdx.x * blockDim.x + threadIdx.x;
    if (i < n) g_deg[gi][i] = 0;
    if (gi == 0 && blockIdx.x == 0 && threadIdx.x < 2 * D) g_colsum[threadIdx.x] = 0.f;
}

// degree count: 4 edges per thread via int4
__global__ void k_count(const int* __restrict__ d0, const int* __restrict__ d1,
                        int e0, int e1) {
    int gi = blockIdx.y;
    const int* __restrict__ dst = gi ? d1 : d0;
    int e = gi ? e1 : e0;
    int i0 = 4 * (blockIdx.x * blockDim.x + threadIdx.x);
    if (i0 + 4 <= e) {
        int4 d = *(const int4*)&dst[i0];
        atomicAdd(&g_deg[gi][d.x], 1);
        atomicAdd(&g_deg[gi][d.y], 1);
        atomicAdd(&g_deg[gi][d.z], 1);
        atomicAdd(&g_deg[gi][d.w], 1);
    } else {
        for (int i = i0; i < e; i++) atomicAdd(&g_deg[gi][dst[i]], 1);
    }
}

__global__ void k_scan(int n) {
    int gi = blockIdx.x;
    const int* __restrict__ deg = g_deg[gi];
    int* __restrict__ rowstart = g_rowstart[gi];
    int* __restrict__ cursor = g_cursor[gi];
    float* __restrict__ invdeg = g_invdeg[gi];

    __shared__ int s_warp[32];
    __shared__ int s_carry;
    int tid = threadIdx.x;
    int lane = tid & 31;
    int wid = tid >> 5;
    if (tid == 0) s_carry = 0;
    __syncthreads();

    for (int base = 0; base < n; base += 1024) {
        int i = base + tid;
        int v = (i < n) ? deg[i] : 0;
        int s = v;
        #pragma unroll
        for (int d = 1; d < 32; d <<= 1) {
            int t = __shfl_up_sync(0xffffffffu, s, d);
            if (lane >= d) s += t;
        }
        if (lane == 31) s_warp[wid] = s;
        __syncthreads();
        if (wid == 0) {
            int w = s_warp[lane];
            #pragma unroll
            for (int d = 1; d < 32; d <<= 1) {
                int t = __shfl_up_sync(0xffffffffu, w, d);
                if (lane >= d) w += t;
            }
            s_warp[lane] = w;
        }
        __syncthreads();
        int carry = s_carry;
        int excl = carry + (wid ? s_warp[wid - 1] : 0) + s - v;
        if (i < n) {
            rowstart[i] = excl;
            cursor[i]   = excl;
            invdeg[i]   = 1.0f / fmaxf((float)v, 1.0f);
        }
        __syncthreads();
        if (tid == 0) s_carry = carry + s_warp[31];
        __syncthreads();
    }
    if (tid == 0) rowstart[n] = s_carry;
}

// CSR fill: 4 edges per thread via int4
__global__ void k_fill(const int* __restrict__ s0, const int* __restrict__ d0,
                       const int* __restrict__ s1, const int* __restrict__ d1,
                       int e0, int e1) {
    int gi = blockIdx.y;
    const int* __restrict__ src = gi ? s1 : s0;
    const int* __restrict__ dst = gi ? d1 : d0;
    int e = gi ? e1 : e0;
    int* __restrict__ cursor = g_cursor[gi];
    int* __restrict__ csr = g_csr[gi];
    int i0 = 4 * (blockIdx.x * blockDim.x + threadIdx.x);
    if (i0 + 4 <= e) {
        int4 d = *(const int4*)&dst[i0];
        int4 s = *(const int4*)&src[i0];
        int p0 = atomicAdd(&cursor[d.x], 1);
        int p1 = atomicAdd(&cursor[d.y], 1);
        int p2 = atomicAdd(&cursor[d.z], 1);
        int p3 = atomicAdd(&cursor[d.w], 1);
        csr[p0] = s.x;
        csr[p1] = s.y;
        csr[p2] = s.z;
        csr[p3] = s.w;
    } else {
        for (int i = i0; i < e; i++) {
            int p = atomicAdd(&cursor[dst[i]], 1);
            csr[p] = src[i];
        }
    }
}

__global__ void k_feat2h(const float* __restrict__ f0, const float* __restrict__ f1, int n) {
    int gi = blockIdx.y;
    const float2* __restrict__ f = (const float2*)(gi ? f1 : f0);
    int i = blockIdx.x * blockDim.x + threadIdx.x;
    if (i < n * H) {
        float2 v = f[i];
        g_bufh[gi][0][i] = __floats2bfloat162_rn(v.x, v.y);
    }
}

// fused aggregate (mean, LDG.64 bf16 gathers, packed f32x2 adds) + GEMM + bias.
// 128 threads, T=16 nodes/block: warp g handles nodes base+4g..base+4g+3 (full 128-col row
// per warp, c4 = lane covers floats [4c4, 4c4+4)). GEMM: thread = out feature, 16 nodes.
__global__ void __launch_bounds__(128, 8) k_layer(
    int sel_in, int sel_out,
    const float* __restrict__ W, const float* __restrict__ bias, int n, int last_layer)
{
    int gi = blockIdx.y;
    const __nv_bfloat162* __restrict__ h_in = g_bufh[gi][sel_in];
    __nv_bfloat162* __restrict__ h_out = g_bufh[gi][sel_out];
    const int* __restrict__ rowstart = g_rowstart[gi];
    const int* __restrict__ csr = g_csr[gi];
    const float* __restrict__ invdeg = g_invdeg[gi];

    __shared__ float rows[D][RP];
    int tid = threadIdx.x;
    int c4  = tid & 31;
    int g   = tid >> 5;
    int base = blockIdx.x * T;
    const unsigned long long one2 = pack2(1.0f, 1.0f);

    #pragma unroll
    for (int t = 0; t < 4; t++) {
        int node = base + 4 * g + t;
        float r0 = 0.f, r1 = 0.f, r2 = 0.f, r3 = 0.f;
        if (node < n) {
            int s = rowstart[node];
            int e = rowstart[node + 1];
            unsigned long long aA0 = 0, aB0 = 0, aA1 = 0, aB1 = 0;
            int i = s;
            for (; i + 4 <= e; i += 4) {
                int c0 = csr[i], c1 = csr[i + 1], cA = csr[i + 2], c3 = csr[i + 3];
                uint2 u0 = __ldcg((const uint2*)&h_in[(size_t)c0 * H + 2 * c4]);
                uint2 u1 = __ldcg((const uint2*)&h_in[(size_t)c1 * H + 2 * c4]);
                uint2 u2 = __ldcg((const uint2*)&h_in[(size_t)cA * H + 2 * c4]);
                uint2 u3 = __ldcg((const uint2*)&h_in[(size_t)c3 * H + 2 * c4]);
                aA0 = fma2(bfpair(u0.x), one2, aA0);
                aB0 = fma2(bfpair(u0.y), one2, aB0);
                aA1 = fma2(bfpair(u1.x), one2, aA1);
                aB1 = fma2(bfpair(u1.y), one2, aB1);
                aA0 = fma2(bfpair(u2.x), one2, aA0);
                aB0 = fma2(bfpair(u2.y), one2, aB0);
                aA1 = fma2(bfpair(u3.x), one2, aA1);
                aB1 = fma2(bfpair(u3.y), one2, aB1);
            }
            for (; i < e; i++) {
                uint2 u = __ldcg((const uint2*)&h_in[(size_t)csr[i] * H + 2 * c4]);
                aA0 = fma2(bfpair(u.x), one2, aA0);
                aB0 = fma2(bfpair(u.y), one2, aB0);
            }
            float x0, x1, y0, y1, x2, x3, y2, y3;
            unpack2(aA0, x0, x1);
            unpack2(aA1, x2, x3);
            unpack2(aB0, y0, y1);
            unpack2(aB1, y2, y3);
            float id = invdeg[node];
            r0 = (x0 + x2) * id;
            r1 = (x1 + x3) * id;
            r2 = (y0 + y2) * id;
            r3 = (y1 + y3) * id;
        }
        int tt = 4 * g + t;
        rows[4 * c4 + 0][tt] = r0;
        rows[4 * c4 + 1][tt] = r1;
        rows[4 * c4 + 2][tt] = r2;
        rows[4 * c4 + 3][tt] = r3;
    }
    __syncthreads();

    // GEMM: out[node][tid] = sum_k rows[k][node] * W[k][tid] + b[tid], 16 nodes/thread
    float bv = bias[tid];
    unsigned long long a0 = pack2(bv, bv);
    unsigned long long a1 = a0, a2 = a0, a3 = a0, a4 = a0, a5 = a0, a6 = a0, a7 = a0;

    #pragma unroll 4
    for (int k = 0; k < D; k++) {
        float wv = W[k * D + tid];
        unsigned long long w2 = pack2(wv, wv);
        const ulonglong2* rp = (const ulonglong2*)&rows[k][0];
        ulonglong2 rA = rp[0];
        ulonglong2 rB = rp[1];
        ulonglong2 rC = rp[2];
        ulonglong2 rD = rp[3];
        a0 = fma2(rA.x, w2, a0);
        a1 = fma2(rA.y, w2, a1);
        a2 = fma2(rB.x, w2, a2);
        a3 = fma2(rB.y, w2, a3);
        a4 = fma2(rC.x, w2, a4);
        a5 = fma2(rC.y, w2, a5);
        a6 = fma2(rD.x, w2, a6);
        a7 = fma2(rD.y, w2, a7);
    }

    float o[T];
    unpack2(a0, o[0],  o[1]);
    unpack2(a1, o[2],  o[3]);
    unpack2(a2, o[4],  o[5]);
    unpack2(a3, o[6],  o[7]);
    unpack2(a4, o[8],  o[9]);
    unpack2(a5, o[10], o[11]);
    unpack2(a6, o[12], o[13]);
    unpack2(a7, o[14], o[15]);

    if (last_layer) {
        float csum = 0.f;
        #pragma unroll
        for (int t = 0; t < T; t++)
            if (base + t < n) csum += o[t];
        atomicAdd(&g_colsum[gi * D + tid], csum);
    } else {
        #pragma unroll
        for (int t = 0; t < T; t++) {
            float hi = __shfl_xor_sync(0xffffffffu, o[t], 1);
            int node = base + t;
            if (!(tid & 1) && node < n)
                h_out[(size_t)node * H + (tid >> 1)] = __floats2bfloat162_rn(o[t], hi);
        }
    }
}

__global__ void k_match(const float* __restrict__ Wr,  const float* __restrict__ br,
                        const float* __restrict__ Wm1, const float* __restrict__ bm1,
                        const float* __restrict__ Wm2, const float* __restrict__ bm2,
                        float n_nodes, float* __restrict__ out)
{
    __shared__ float c[2 * D];
    __shared__ float red[D];
    int tid = threadIdx.x;
    int g = tid / D;
    int j = tid % D;
    float invn = 1.0f / n_nodes;

    float acc = br[j];
    for (int k = 0; k < D; k++)
        acc += (g_colsum[g * D + k] * invn) * Wr[k * D + j];
    c[tid] = 1.0f / (1.0f + expf(-acc));
    __syncthreads();

    if (tid < D) {
        float d1 = bm1[tid];
        for (int i = 0; i < 2 * D; i++)
            d1 += c[i] * Wm1[i * D + tid];
        red[tid] = d1 * Wm2[tid];
    }
    __syncthreads();

    if (tid == 0) {
        float s = 0.f;
        for (int i = 0; i < D; i++) s += red[i];
        out[0] = 1.0f / (1.0f + expf(-(s + bm2[0])));
    }
}

extern "C" void kernel_launch(void* const* d_in, const int* in_sizes, int n_in,
                              void* d_out, int out_size)
{
    const float* feat_p = (const float*)d_in[0];
    const int*   src_p  = (const int*)d_in[1];
    const int*   dst_p  = (const int*)d_in[2];
    const float* feat_s = (const float*)d_in[3];
    const int*   src_s  = (const int*)d_in[4];
    const int*   dst_s  = (const int*)d_in[5];
    const float* W[3]   = { (const float*)d_in[6], (const float*)d_in[8], (const float*)d_in[10] };
    const float* b[3]   = { (const float*)d_in[7], (const float*)d_in[9], (const float*)d_in[11] };
    const float* Wr  = (const float*)d_in[12];
    const float* br  = (const float*)d_in[13];
    const float* Wm1 = (const float*)d_in[14];
    const float* bm1 = (const float*)d_in[15];
    const float* Wm2 = (const float*)d_in[16];
    const float* bm2 = (const float*)d_in[17];

    int n  = in_sizes[0] / D;
    int e0 = in_sizes[1];
    int e1 = in_sizes[4];
    int emax = e0 > e1 ? e0 : e1;

    dim3 gN((n + 511) / 512, 2);
    dim3 gE4(((emax + 3) / 4 + 511) / 512, 2);
    dim3 gF((n * H + 255) / 256, 2);

    k_init<<<gN, 512>>>(n);
    k_count<<<gE4, 512>>>(dst_p, dst_s, e0, e1);
    k_scan<<<2, 1024>>>(n);
    k_fill<<<gE4, 512>>>(src_p, dst_p, src_s, dst_s, e0, e1);
    k_feat2h<<<gF, 256>>>(feat_p, feat_s, n);

    dim3 gL((n + T - 1) / T, 2);
    k_layer<<<gL, 128>>>(0, 1, W[0], b[0], n, 0);   // feat(bf16) -> buf1
    k_layer<<<gL, 128>>>(1, 0, W[1], b[1], n, 0);   // buf1 -> buf0
    k_layer<<<gL, 128>>>(0, 1, W[2], b[2], n, 1);   // buf0 -> colsum only

    k_match<<<1, 256>>>(Wr, br, Wm1, bm1, Wm2, bm2, (float)n, (float*)d_out);
}

// round 10
// speedup vs baseline: 3.2472x; 1.0245x over previous
#include <cuda_runtime.h>
#include <cuda_bf16.h>
#include <math.h>

#define NMAX 50000
#define EMAX 1600000
#define D 128
#define H (D/2)
#define T 16
#define RP 20   // 80B smem row stride: 16B-aligned ulonglong2 loads at offsets 0/4/8/12

__device__ __nv_bfloat162 g_bufh[2][2][NMAX * H];
__device__ int   g_deg[2][NMAX];
__device__ int   g_rowstart[2][NMAX + 1];
__device__ int   g_cursor[2][NMAX];
__device__ int   g_csr[2][EMAX];
__device__ float g_invdeg[2][NMAX];
__device__ float g_colsum[2 * D];

__device__ __forceinline__ unsigned long long pack2(float lo, float hi) {
    unsigned long long r;
    asm("mov.b64 %0, {%1, %2};" : "=l"(r) : "f"(lo), "f"(hi));
    return r;
}
__device__ __forceinline__ void unpack2(unsigned long long v, float& lo, float& hi) {
    asm("mov.b64 {%0, %1}, %2;" : "=f"(lo), "=f"(hi) : "l"(v));
}
__device__ __forceinline__ unsigned long long fma2(unsigned long long a,
                                                   unsigned long long b,
                                                   unsigned long long c) {
    unsigned long long d;
    asm("fma.rn.f32x2 %0, %1, %2, %3;" : "=l"(d) : "l"(a), "l"(b), "l"(c));
    return d;
}
__device__ __forceinline__ unsigned long long bfpair(unsigned u) {
    float lo = __int_as_float(u << 16);
    float hi = __int_as_float(u & 0xffff0000u);
    return pack2(lo, hi);
}

__global__ void k_init(int n) {
    int gi = blockIdx.y;
    int i = blockIdx.x * blockDim.x + threadIdx.x;
    if (i < n) g_deg[gi][i] = 0;
    if (gi == 0 && blockIdx.x == 0 && threadIdx.x < 2 * D) g_colsum[threadIdx.x] = 0.f;
}

// degree count: 8 edges per thread via 2x int4 (MLP 8)
__global__ void k_count(const int* __restrict__ d0, const int* __restrict__ d1,
                        int e0, int e1) {
    int gi = blockIdx.y;
    const int* __restrict__ dst = gi ? d1 : d0;
    int e = gi ? e1 : e0;
    int i0 = 8 * (blockIdx.x * blockDim.x + threadIdx.x);
    if (i0 + 8 <= e) {
        int4 a = *(const int4*)&dst[i0];
        int4 b = *(const int4*)&dst[i0 + 4];
        atomicAdd(&g_deg[gi][a.x], 1);
        atomicAdd(&g_deg[gi][a.y], 1);
        atomicAdd(&g_deg[gi][a.z], 1);
        atomicAdd(&g_deg[gi][a.w], 1);
        atomicAdd(&g_deg[gi][b.x], 1);
        atomicAdd(&g_deg[gi][b.y], 1);
        atomicAdd(&g_deg[gi][b.z], 1);
        atomicAdd(&g_deg[gi][b.w], 1);
    } else {
        for (int i = i0; i < e; i++) atomicAdd(&g_deg[gi][dst[i]], 1);
    }
}

__global__ void k_scan(int n) {
    int gi = blockIdx.x;
    const int* __restrict__ deg = g_deg[gi];
    int* __restrict__ rowstart = g_rowstart[gi];
    int* __restrict__ cursor = g_cursor[gi];
    float* __restrict__ invdeg = g_invdeg[gi];

    __shared__ int s_warp[32];
    __shared__ int s_carry;
    int tid = threadIdx.x;
    int lane = tid & 31;
    int wid = tid >> 5;
    if (tid == 0) s_carry = 0;
    __syncthreads();

    for (int base = 0; base < n; base += 1024) {
        int i = base + tid;
        int v = (i < n) ? deg[i] : 0;
        int s = v;
        #pragma unroll
        for (int d = 1; d < 32; d <<= 1) {
            int t = __shfl_up_sync(0xffffffffu, s, d);
            if (lane >= d) s += t;
        }
        if (lane == 31) s_warp[wid] = s;
        __syncthreads();
        if (wid == 0) {
            int w = s_warp[lane];
            #pragma unroll
            for (int d = 1; d < 32; d <<= 1) {
                int t = __shfl_up_sync(0xffffffffu, w, d);
                if (lane >= d) w += t;
            }
            s_warp[lane] = w;
        }
        __syncthreads();
        int carry = s_carry;
        int excl = carry + (wid ? s_warp[wid - 1] : 0) + s - v;
        if (i < n) {
            rowstart[i] = excl;
            cursor[i]   = excl;
            invdeg[i]   = 1.0f / fmaxf((float)v, 1.0f);
        }
        __syncthreads();
        if (tid == 0) s_carry = carry + s_warp[31];
        __syncthreads();
    }
    if (tid == 0) rowstart[n] = s_carry;
}

// CSR fill: 8 edges per thread via 2x int4 (MLP 8 on atomics)
__global__ void k_fill(const int* __restrict__ s0, const int* __restrict__ d0,
                       const int* __restrict__ s1, const int* __restrict__ d1,
                       int e0, int e1) {
    int gi = blockIdx.y;
    const int* __restrict__ src = gi ? s1 : s0;
    const int* __restrict__ dst = gi ? d1 : d0;
    int e = gi ? e1 : e0;
    int* __restrict__ cursor = g_cursor[gi];
    int* __restrict__ csr = g_csr[gi];
    int i0 = 8 * (blockIdx.x * blockDim.x + threadIdx.x);
    if (i0 + 8 <= e) {
        int4 da = *(const int4*)&dst[i0];
        int4 db = *(const int4*)&dst[i0 + 4];
        int4 sa = *(const int4*)&src[i0];
        int4 sb = *(const int4*)&src[i0 + 4];
        int p0 = atomicAdd(&cursor[da.x], 1);
        int p1 = atomicAdd(&cursor[da.y], 1);
        int p2 = atomicAdd(&cursor[da.z], 1);
        int p3 = atomicAdd(&cursor[da.w], 1);
        int p4 = atomicAdd(&cursor[db.x], 1);
        int p5 = atomicAdd(&cursor[db.y], 1);
        int p6 = atomicAdd(&cursor[db.z], 1);
        int p7 = atomicAdd(&cursor[db.w], 1);
        csr[p0] = sa.x;
        csr[p1] = sa.y;
        csr[p2] = sa.z;
        csr[p3] = sa.w;
        csr[p4] = sb.x;
        csr[p5] = sb.y;
        csr[p6] = sb.z;
        csr[p7] = sb.w;
    } else {
        for (int i = i0; i < e; i++) {
            int p = atomicAdd(&cursor[dst[i]], 1);
            csr[p] = src[i];
        }
    }
}

__global__ void k_feat2h(const float* __restrict__ f0, const float* __restrict__ f1, int n) {
    int gi = blockIdx.y;
    const float2* __restrict__ f = (const float2*)(gi ? f1 : f0);
    int i = blockIdx.x * blockDim.x + threadIdx.x;
    if (i < n * H) {
        float2 v = f[i];
        g_bufh[gi][0][i] = __floats2bfloat162_rn(v.x, v.y);
    }
}

// fused aggregate (mean, LDG.64 bf16 gathers MLP=8) + GEMM (f32x2) + bias.
// 128 threads, T=16 nodes/block: warp g handles nodes base+4g..base+4g+3,
// lane c4 covers floats [4c4, 4c4+4). GEMM: thread = out feature, 16 nodes.
__global__ void __launch_bounds__(128, 8) k_layer(
    int sel_in, int sel_out,
    const float* __restrict__ W, const float* __restrict__ bias, int n, int last_layer)
{
    int gi = blockIdx.y;
    const __nv_bfloat162* __restrict__ h_in = g_bufh[gi][sel_in];
    __nv_bfloat162* __restrict__ h_out = g_bufh[gi][sel_out];
    const int* __restrict__ rowstart = g_rowstart[gi];
    const int* __restrict__ csr = g_csr[gi];
    const float* __restrict__ invdeg = g_invdeg[gi];

    __shared__ float rows[D][RP];
    int tid = threadIdx.x;
    int c4  = tid & 31;
    int g   = tid >> 5;
    int base = blockIdx.x * T;
    const unsigned long long one2 = pack2(1.0f, 1.0f);

    #pragma unroll
    for (int t = 0; t < 4; t++) {
        int node = base + 4 * g + t;
        float r0 = 0.f, r1 = 0.f, r2 = 0.f, r3 = 0.f;
        if (node < n) {
            int s = rowstart[node];
            int e = rowstart[node + 1];
            unsigned long long aA0 = 0, aB0 = 0, aA1 = 0, aB1 = 0;
            int i = s;
            // unroll 8: issue 8 independent LDG.64 before consuming (MLP=8)
            for (; i + 8 <= e; i += 8) {
                int c0 = csr[i],     c1 = csr[i + 1], cA = csr[i + 2], c3 = csr[i + 3];
                int c5 = csr[i + 4], c6 = csr[i + 5], c7 = csr[i + 6], c8 = csr[i + 7];
                uint2 u0 = __ldcg((const uint2*)&h_in[(size_t)c0 * H + 2 * c4]);
                uint2 u1 = __ldcg((const uint2*)&h_in[(size_t)c1 * H + 2 * c4]);
                uint2 u2 = __ldcg((const uint2*)&h_in[(size_t)cA * H + 2 * c4]);
                uint2 u3 = __ldcg((const uint2*)&h_in[(size_t)c3 * H + 2 * c4]);
                uint2 u4 = __ldcg((const uint2*)&h_in[(size_t)c5 * H + 2 * c4]);
                uint2 u5 = __ldcg((const uint2*)&h_in[(size_t)c6 * H + 2 * c4]);
                uint2 u6 = __ldcg((const uint2*)&h_in[(size_t)c7 * H + 2 * c4]);
                uint2 u7 = __ldcg((const uint2*)&h_in[(size_t)c8 * H + 2 * c4]);
                aA0 = fma2(bfpair(u0.x), one2, aA0);
                aB0 = fma2(bfpair(u0.y), one2, aB0);
                aA1 = fma2(bfpair(u1.x), one2, aA1);
                aB1 = fma2(bfpair(u1.y), one2, aB1);
                aA0 = fma2(bfpair(u2.x), one2, aA0);
                aB0 = fma2(bfpair(u2.y), one2, aB0);
                aA1 = fma2(bfpair(u3.x), one2, aA1);
                aB1 = fma2(bfpair(u3.y), one2, aB1);
                aA0 = fma2(bfpair(u4.x), one2, aA0);
                aB0 = fma2(bfpair(u4.y), one2, aB0);
                aA1 = fma2(bfpair(u5.x), one2, aA1);
                aB1 = fma2(bfpair(u5.y), one2, aB1);
                aA0 = fma2(bfpair(u6.x), one2, aA0);
                aB0 = fma2(bfpair(u6.y), one2, aB0);
                aA1 = fma2(bfpair(u7.x), one2, aA1);
                aB1 = fma2(bfpair(u7.y), one2, aB1);
            }
            for (; i < e; i++) {
                uint2 u = __ldcg((const uint2*)&h_in[(size_t)csr[i] * H + 2 * c4]);
                aA0 = fma2(bfpair(u.x), one2, aA0);
                aB0 = fma2(bfpair(u.y), one2, aB0);
            }
            float x0, x1, y0, y1, x2, x3, y2, y3;
            unpack2(aA0, x0, x1);
            unpack2(aA1, x2, x3);
            unpack2(aB0, y0, y1);
            unpack2(aB1, y2, y3);
            float id = invdeg[node];
            r0 = (x0 + x2) * id;
            r1 = (x1 + x3) * id;
            r2 = (y0 + y2) * id;
            r3 = (y1 + y3) * id;
        }
        int tt = 4 * g + t;
        rows[4 * c4 + 0][tt] = r0;
        rows[4 * c4 + 1][tt] = r1;
        rows[4 * c4 + 2][tt] = r2;
        rows[4 * c4 + 3][tt] = r3;
    }
    __syncthreads();

    // GEMM: out[node][tid] = sum_k rows[k][node] * W[k][tid] + b[tid], 16 nodes/thread
    float bv = bias[tid];
    unsigned long long a0 = pack2(bv, bv);
    unsigned long long a1 = a0, a2 = a0, a3 = a0, a4 = a0, a5 = a0, a6 = a0, a7 = a0;

    #pragma unroll 4
    for (int k = 0; k < D; k++) {
        float wv = W[k * D + tid];
        unsigned long long w2 = pack2(wv, wv);
        const ulonglong2* rp = (const ulonglong2*)&rows[k][0];
        ulonglong2 rA = rp[0];
        ulonglong2 rB = rp[1];
        ulonglong2 rC = rp[2];
        ulonglong2 rD = rp[3];
        a0 = fma2(rA.x, w2, a0);
        a1 = fma2(rA.y, w2, a1);
        a2 = fma2(rB.x, w2, a2);
        a3 = fma2(rB.y, w2, a3);
        a4 = fma2(rC.x, w2, a4);
        a5 = fma2(rC.y, w2, a5);
        a6 = fma2(rD.x, w2, a6);
        a7 = fma2(rD.y, w2, a7);
    }

    float o[T];
    unpack2(a0, o[0],  o[1]);
    unpack2(a1, o[2],  o[3]);
    unpack2(a2, o[4],  o[5]);
    unpack2(a3, o[6],  o[7]);
    unpack2(a4, o[8],  o[9]);
    unpack2(a5, o[10], o[11]);
    unpack2(a6, o[12], o[13]);
    unpack2(a7, o[14], o[15]);

    if (last_layer) {
        float csum = 0.f;
        #pragma unroll
        for (int t = 0; t < T; t++)
            if (base + t < n) csum += o[t];
        atomicAdd(&g_colsum[gi * D + tid], csum);
    } else {
        #pragma unroll
        for (int t = 0; t < T; t++) {
            float hi = __shfl_xor_sync(0xffffffffu, o[t], 1);
            int node = base + t;
            if (!(tid & 1) && node < n)
                h_out[(size_t)node * H + (tid >> 1)] = __floats2bfloat162_rn(o[t], hi);
        }
    }
}

__global__ void k_match(const float* __restrict__ Wr,  const float* __restrict__ br,
                        const float* __restrict__ Wm1, const float* __restrict__ bm1,
                        const float* __restrict__ Wm2, const float* __restrict__ bm2,
                        float n_nodes, float* __restrict__ out)
{
    __shared__ float c[2 * D];
    __shared__ float red[D];
    int tid = threadIdx.x;
    int g = tid / D;
    int j = tid % D;
    float invn = 1.0f / n_nodes;

    float acc = br[j];
    for (int k = 0; k < D; k++)
        acc += (g_colsum[g * D + k] * invn) * Wr[k * D + j];
    c[tid] = 1.0f / (1.0f + expf(-acc));
    __syncthreads();

    if (tid < D) {
        float d1 = bm1[tid];
        for (int i = 0; i < 2 * D; i++)
            d1 += c[i] * Wm1[i * D + tid];
        red[tid] = d1 * Wm2[tid];
    }
    __syncthreads();

    if (tid == 0) {
        float s = 0.f;
        for (int i = 0; i < D; i++) s += red[i];
        out[0] = 1.0f / (1.0f + expf(-(s + bm2[0])));
    }
}

extern "C" void kernel_launch(void* const* d_in, const int* in_sizes, int n_in,
                              void* d_out, int out_size)
{
    const float* feat_p = (const float*)d_in[0];
    const int*   src_p  = (const int*)d_in[1];
    const int*   dst_p  = (const int*)d_in[2];
    const float* feat_s = (const float*)d_in[3];
    const int*   src_s  = (const int*)d_in[4];
    const int*   dst_s  = (const int*)d_in[5];
    const float* W[3]   = { (const float*)d_in[6], (const float*)d_in[8], (const float*)d_in[10] };
    const float* b[3]   = { (const float*)d_in[7], (const float*)d_in[9], (const float*)d_in[11] };
    const float* Wr  = (const float*)d_in[12];
    const float* br  = (const float*)d_in[13];
    const float* Wm1 = (const float*)d_in[14];
    const float* bm1 = (const float*)d_in[15];
    const float* Wm2 = (const float*)d_in[16];
    const float* bm2 = (const float*)d_in[17];

    int n  = in_sizes[0] / D;
    int e0 = in_sizes[1];
    int e1 = in_sizes[4];
    int emax = e0 > e1 ? e0 : e1;

    dim3 gN((n + 511) / 512, 2);
    dim3 gE8(((emax + 7) / 8 + 511) / 512, 2);
    dim3 gF((n * H + 255) / 256, 2);

    k_init<<<gN, 512>>>(n);
    k_count<<<gE8, 512>>>(dst_p, dst_s, e0, e1);
    k_scan<<<2, 1024>>>(n);
    k_fill<<<gE8, 512>>>(src_p, dst_p, src_s, dst_s, e0, e1);
    k_feat2h<<<gF, 256>>>(feat_p, feat_s, n);

    dim3 gL((n + T - 1) / T, 2);
    k_layer<<<gL, 128>>>(0, 1, W[0], b[0], n, 0);   // feat(bf16) -> buf1
    k_layer<<<gL, 128>>>(1, 0, W[1], b[1], n, 0);   // buf1 -> buf0
    k_layer<<<gL, 128>>>(0, 1, W[2], b[2], n, 1);   // buf0 -> colsum only

    k_match<<<1, 256>>>(Wr, br, Wm1, bm1, Wm2, bm2, (float)n, (float*)d_out);
}

// round 11
// speedup vs baseline: 3.4277x; 1.0556x over previous
#include <cuda_runtime.h>
#include <cuda_fp16.h>
#include <math.h>

#define NMAX 50000
#define EMAX 1600000
#define D 128
#define HW 32    // packed fp8x4 words per node row (128 cols * 1B / 4)
#define T 16
#define RP 20    // 80B smem row stride: 16B-aligned ulonglong2 loads

__device__ unsigned g_buf8[2][2][NMAX * HW];   // [graph][ping-pong][N*32] fp8x4 words
__device__ int   g_deg[2][NMAX];
__device__ int   g_rowstart[2][NMAX + 1];
__device__ int   g_cursor[2][NMAX];
__device__ int   g_csr[2][EMAX];
__device__ float g_invdeg[2][NMAX];
__device__ float g_colsum[2 * D];

// ---- packed math helpers ----
__device__ __forceinline__ unsigned long long pack2(float lo, float hi) {
    unsigned long long r;
    asm("mov.b64 %0, {%1, %2};" : "=l"(r) : "f"(lo), "f"(hi));
    return r;
}
__device__ __forceinline__ void unpack2(unsigned long long v, float& lo, float& hi) {
    asm("mov.b64 {%0, %1}, %2;" : "=f"(lo), "=f"(hi) : "l"(v));
}
__device__ __forceinline__ unsigned long long fma2(unsigned long long a,
                                                   unsigned long long b,
                                                   unsigned long long c) {
    unsigned long long d;
    asm("fma.rn.f32x2 %0, %1, %2, %3;" : "=l"(d) : "l"(a), "l"(b), "l"(c));
    return d;
}
// 4 fp8 (e4m3) in a u32 -> two half2
__device__ __forceinline__ void fp8x4_to_h2(unsigned u, __half2& a, __half2& b) {
    unsigned short h0, h1;
    asm("mov.b32 {%0, %1}, %2;" : "=h"(h0), "=h"(h1) : "r"(u));
    unsigned r0, r1;
    asm("cvt.rn.f16x2.e4m3x2 %0, %1;" : "=r"(r0) : "h"(h0));
    asm("cvt.rn.f16x2.e4m3x2 %0, %1;" : "=r"(r1) : "h"(h1));
    a = *reinterpret_cast<__half2*>(&r0);
    b = *reinterpret_cast<__half2*>(&r1);
}
// two floats -> fp8x2 (lo = first arg)
__device__ __forceinline__ unsigned short f2_to_fp8x2(float lo, float hi) {
    unsigned short r;
    asm("cvt.rn.satfinite.e4m3x2.f32 %0, %1, %2;" : "=h"(r) : "f"(hi), "f"(lo));
    return r;
}

__global__ void k_init(int n) {
    int gi = blockIdx.y;
    int i = blockIdx.x * blockDim.x + threadIdx.x;
    if (i < n) g_deg[gi][i] = 0;
    if (gi == 0 && blockIdx.x == 0 && threadIdx.x < 2 * D) g_colsum[threadIdx.x] = 0.f;
}

__global__ void k_count(const int* __restrict__ d0, const int* __restrict__ d1,
                        int e0, int e1) {
    int gi = blockIdx.y;
    const int* __restrict__ dst = gi ? d1 : d0;
    int e = gi ? e1 : e0;
    int i0 = 8 * (blockIdx.x * blockDim.x + threadIdx.x);
    if (i0 + 8 <= e) {
        int4 a = *(const int4*)&dst[i0];
        int4 b = *(const int4*)&dst[i0 + 4];
        atomicAdd(&g_deg[gi][a.x], 1);
        atomicAdd(&g_deg[gi][a.y], 1);
        atomicAdd(&g_deg[gi][a.z], 1);
        atomicAdd(&g_deg[gi][a.w], 1);
        atomicAdd(&g_deg[gi][b.x], 1);
        atomicAdd(&g_deg[gi][b.y], 1);
        atomicAdd(&g_deg[gi][b.z], 1);
        atomicAdd(&g_deg[gi][b.w], 1);
    } else {
        for (int i = i0; i < e; i++) atomicAdd(&g_deg[gi][dst[i]], 1);
    }
}

__global__ void k_scan(int n) {
    int gi = blockIdx.x;
    const int* __restrict__ deg = g_deg[gi];
    int* __restrict__ rowstart = g_rowstart[gi];
    int* __restrict__ cursor = g_cursor[gi];
    float* __restrict__ invdeg = g_invdeg[gi];

    __shared__ int s_warp[32];
    __shared__ int s_carry;
    int tid = threadIdx.x;
    int lane = tid & 31;
    int wid = tid >> 5;
    if (tid == 0) s_carry = 0;
    __syncthreads();

    for (int base = 0; base < n; base += 1024) {
        int i = base + tid;
        int v = (i < n) ? deg[i] : 0;
        int s = v;
        #pragma unroll
        for (int d = 1; d < 32; d <<= 1) {
            int t = __shfl_up_sync(0xffffffffu, s, d);
            if (lane >= d) s += t;
        }
        if (lane == 31) s_warp[wid] = s;
        __syncthreads();
        if (wid == 0) {
            int w = s_warp[lane];
            #pragma unroll
            for (int d = 1; d < 32; d <<= 1) {
                int t = __shfl_up_sync(0xffffffffu, w, d);
                if (lane >= d) w += t;
            }
            s_warp[lane] = w;
        }
        __syncthreads();
        int carry = s_carry;
        int excl = carry + (wid ? s_warp[wid - 1] : 0) + s - v;
        if (i < n) {
            rowstart[i] = excl;
            cursor[i]   = excl;
            invdeg[i]   = 1.0f / fmaxf((float)v, 1.0f);
        }
        __syncthreads();
        if (tid == 0) s_carry = carry + s_warp[31];
        __syncthreads();
    }
    if (tid == 0) rowstart[n] = s_carry;
}

__global__ void k_fill(const int* __restrict__ s0, const int* __restrict__ d0,
                       const int* __restrict__ s1, const int* __restrict__ d1,
                       int e0, int e1) {
    int gi = blockIdx.y;
    const int* __restrict__ src = gi ? s1 : s0;
    const int* __restrict__ dst = gi ? d1 : d0;
    int e = gi ? e1 : e0;
    int* __restrict__ cursor = g_cursor[gi];
    int* __restrict__ csr = g_csr[gi];
    int i0 = 8 * (blockIdx.x * blockDim.x + threadIdx.x);
    if (i0 + 8 <= e) {
        int4 da = *(const int4*)&dst[i0];
        int4 db = *(const int4*)&dst[i0 + 4];
        int4 sa = *(const int4*)&src[i0];
        int4 sb = *(const int4*)&src[i0 + 4];
        int p0 = atomicAdd(&cursor[da.x], 1);
        int p1 = atomicAdd(&cursor[da.y], 1);
        int p2 = atomicAdd(&cursor[da.z], 1);
        int p3 = atomicAdd(&cursor[da.w], 1);
        int p4 = atomicAdd(&cursor[db.x], 1);
        int p5 = atomicAdd(&cursor[db.y], 1);
        int p6 = atomicAdd(&cursor[db.z], 1);
        int p7 = atomicAdd(&cursor[db.w], 1);
        csr[p0] = sa.x;
        csr[p1] = sa.y;
        csr[p2] = sa.z;
        csr[p3] = sa.w;
        csr[p4] = sb.x;
        csr[p5] = sb.y;
        csr[p6] = sb.z;
        csr[p7] = sb.w;
    } else {
        for (int i = i0; i < e; i++) {
            int p = atomicAdd(&cursor[dst[i]], 1);
            csr[p] = src[i];
        }
    }
}

// convert input features fp32 -> packed fp8x4 words
__global__ void k_feat2h(const float* __restrict__ f0, const float* __restrict__ f1, int n) {
    int gi = blockIdx.y;
    const float4* __restrict__ f = (const float4*)(gi ? f1 : f0);
    int i = blockIdx.x * blockDim.x + threadIdx.x;
    if (i < n * HW) {
        float4 v = f[i];
        unsigned short lo = f2_to_fp8x2(v.x, v.y);
        unsigned short hi = f2_to_fp8x2(v.z, v.w);
        g_buf8[gi][0][i] = (unsigned)lo | ((unsigned)hi << 16);
    }
}

// fused aggregate (mean, LDG.32 fp8x4 gathers, half2 accumulate) + GEMM (f32x2) + bias.
// 128 threads, T=16 nodes/block: warp g handles nodes base+4g..base+4g+3,
// lane covers cols [4*lane, 4*lane+4). GEMM: thread = out feature, 16 nodes.
__global__ void __launch_bounds__(128, 8) k_layer(
    int sel_in, int sel_out,
    const float* __restrict__ W, const float* __restrict__ bias, int n, int last_layer)
{
    int gi = blockIdx.y;
    const unsigned* __restrict__ h_in = g_buf8[gi][sel_in];
    unsigned* __restrict__ h_out = g_buf8[gi][sel_out];
    const int* __restrict__ rowstart = g_rowstart[gi];
    const int* __restrict__ csr = g_csr[gi];
    const float* __restrict__ invdeg = g_invdeg[gi];

    __shared__ float rows[D][RP];
    int tid = threadIdx.x;
    int lane = tid & 31;
    int g    = tid >> 5;
    int base = blockIdx.x * T;

    #pragma unroll
    for (int t = 0; t < 4; t++) {
        int node = base + 4 * g + t;
        float r0 = 0.f, r1 = 0.f, r2 = 0.f, r3 = 0.f;
        if (node < n) {
            int s = rowstart[node];
            int e = rowstart[node + 1];
            __half2 z = __float2half2_rn(0.f);
            __half2 aA = z, aB = z, bA = z, bB = z;   // 2 col-pairs x 2 interleave
            int i = s;
            // unroll 8: 8 independent LDG.32 in flight (MLP 8)
            for (; i + 8 <= e; i += 8) {
                int c0 = csr[i],     c1 = csr[i + 1], c2 = csr[i + 2], c3 = csr[i + 3];
                int c4 = csr[i + 4], c5 = csr[i + 5], c6 = csr[i + 6], c7 = csr[i + 7];
                unsigned u0 = __ldcg(&h_in[(size_t)c0 * HW + lane]);
                unsigned u1 = __ldcg(&h_in[(size_t)c1 * HW + lane]);
                unsigned u2 = __ldcg(&h_in[(size_t)c2 * HW + lane]);
                unsigned u3 = __ldcg(&h_in[(size_t)c3 * HW + lane]);
                unsigned u4 = __ldcg(&h_in[(size_t)c4 * HW + lane]);
                unsigned u5 = __ldcg(&h_in[(size_t)c5 * HW + lane]);
                unsigned u6 = __ldcg(&h_in[(size_t)c6 * HW + lane]);
                unsigned u7 = __ldcg(&h_in[(size_t)c7 * HW + lane]);
                __half2 p0a, p0b, p1a, p1b, p2a, p2b, p3a, p3b;
                fp8x4_to_h2(u0, p0a, p0b);
                fp8x4_to_h2(u1, p1a, p1b);
                fp8x4_to_h2(u2, p2a, p2b);
                fp8x4_to_h2(u3, p3a, p3b);
                aA = __hadd2(aA, p0a); aB = __hadd2(aB, p0b);
                bA = __hadd2(bA, p1a); bB = __hadd2(bB, p1b);
                aA = __hadd2(aA, p2a); aB = __hadd2(aB, p2b);
                bA = __hadd2(bA, p3a); bB = __hadd2(bB, p3b);
                fp8x4_to_h2(u4, p0a, p0b);
                fp8x4_to_h2(u5, p1a, p1b);
                fp8x4_to_h2(u6, p2a, p2b);
                fp8x4_to_h2(u7, p3a, p3b);
                aA = __hadd2(aA, p0a); aB = __hadd2(aB, p0b);
                bA = __hadd2(bA, p1a); bB = __hadd2(bB, p1b);
                aA = __hadd2(aA, p2a); aB = __hadd2(aB, p2b);
                bA = __hadd2(bA, p3a); bB = __hadd2(bB, p3b);
            }
            for (; i < e; i++) {
                unsigned u = __ldcg(&h_in[(size_t)csr[i] * HW + lane]);
                __half2 pa, pb;
                fp8x4_to_h2(u, pa, pb);
                aA = __hadd2(aA, pa);
                aB = __hadd2(aB, pb);
            }
            float2 fA = __half22float2(__hadd2(aA, bA));
            float2 fB = __half22float2(__hadd2(aB, bB));
            float id = invdeg[node];
            r0 = fA.x * id;
            r1 = fA.y * id;
            r2 = fB.x * id;
            r3 = fB.y * id;
        }
        int tt = 4 * g + t;
        rows[4 * lane + 0][tt] = r0;
        rows[4 * lane + 1][tt] = r1;
        rows[4 * lane + 2][tt] = r2;
        rows[4 * lane + 3][tt] = r3;
    }
    __syncthreads();

    // GEMM: out[node][tid] = sum_k rows[k][node] * W[k][tid] + b[tid], 16 nodes/thread
    float bv = bias[tid];
    unsigned long long a0 = pack2(bv, bv);
    unsigned long long a1 = a0, a2 = a0, a3 = a0, a4 = a0, a5 = a0, a6 = a0, a7 = a0;

    #pragma unroll 4
    for (int k = 0; k < D; k++) {
        float wv = W[k * D + tid];
        unsigned long long w2 = pack2(wv, wv);
        const ulonglong2* rp = (const ulonglong2*)&rows[k][0];
        ulonglong2 rA = rp[0];
        ulonglong2 rB = rp[1];
        ulonglong2 rC = rp[2];
        ulonglong2 rD = rp[3];
        a0 = fma2(rA.x, w2, a0);
        a1 = fma2(rA.y, w2, a1);
        a2 = fma2(rB.x, w2, a2);
        a3 = fma2(rB.y, w2, a3);
        a4 = fma2(rC.x, w2, a4);
        a5 = fma2(rC.y, w2, a5);
        a6 = fma2(rD.x, w2, a6);
        a7 = fma2(rD.y, w2, a7);
    }

    float o[T];
    unpack2(a0, o[0],  o[1]);
    unpack2(a1, o[2],  o[3]);
    unpack2(a2, o[4],  o[5]);
    unpack2(a3, o[6],  o[7]);
    unpack2(a4, o[8],  o[9]);
    unpack2(a5, o[10], o[11]);
    unpack2(a6, o[12], o[13]);
    unpack2(a7, o[14], o[15]);

    if (last_layer) {
        float csum = 0.f;
        #pragma unroll
        for (int t = 0; t < T; t++)
            if (base + t < n) csum += o[t];
        atomicAdd(&g_colsum[gi * D + tid], csum);
    } else {
        // pack 4 adjacent output features into one fp8x4 word; threads tid%4==0 store
        #pragma unroll
        for (int t = 0; t < T; t++) {
            float nb = __shfl_xor_sync(0xffffffffu, o[t], 1);
            unsigned short pr = f2_to_fp8x2(o[t], nb);     // (tid, tid^1): even tid has (lo,hi) correct
            unsigned pr32 = pr;
            unsigned other = __shfl_xor_sync(0xffffffffu, pr32, 2);
            int node = base + t;
            if ((tid & 3) == 0 && node < n)
                h_out[(size_t)node * HW + (tid >> 2)] = pr32 | (other << 16);
        }
    }
}

__global__ void k_match(const float* __restrict__ Wr,  const float* __restrict__ br,
                        const float* __restrict__ Wm1, const float* __restrict__ bm1,
                        const float* __restrict__ Wm2, const float* __restrict__ bm2,
                        float n_nodes, float* __restrict__ out)
{
    __shared__ float c[2 * D];
    __shared__ float red[D];
    int tid = threadIdx.x;
    int g = tid / D;
    int j = tid % D;
    float invn = 1.0f / n_nodes;

    float acc = br[j];
    for (int k = 0; k < D; k++)
        acc += (g_colsum[g * D + k] * invn) * Wr[k * D + j];
    c[tid] = 1.0f / (1.0f + expf(-acc));
    __syncthreads();

    if (tid < D) {
        float d1 = bm1[tid];
        for (int i = 0; i < 2 * D; i++)
            d1 += c[i] * Wm1[i * D + tid];
        red[tid] = d1 * Wm2[tid];
    }
    __syncthreads();

    if (tid == 0) {
        float s = 0.f;
        for (int i = 0; i < D; i++) s += red[i];
        out[0] = 1.0f / (1.0f + expf(-(s + bm2[0])));
    }
}

extern "C" void kernel_launch(void* const* d_in, const int* in_sizes, int n_in,
                              void* d_out, int out_size)
{
    const float* feat_p = (const float*)d_in[0];
    const int*   src_p  = (const int*)d_in[1];
    const int*   dst_p  = (const int*)d_in[2];
    const float* feat_s = (const float*)d_in[3];
    const int*   src_s  = (const int*)d_in[4];
    const int*   dst_s  = (const int*)d_in[5];
    const float* W[3]   = { (const float*)d_in[6], (const float*)d_in[8], (const float*)d_in[10] };
    const float* b[3]   = { (const float*)d_in[7], (const float*)d_in[9], (const float*)d_in[11] };
    const float* Wr  = (const float*)d_in[12];
    const float* br  = (const float*)d_in[13];
    const float* Wm1 = (const float*)d_in[14];
    const float* bm1 = (const float*)d_in[15];
    const float* Wm2 = (const float*)d_in[16];
    const float* bm2 = (const float*)d_in[17];

    int n  = in_sizes[0] / D;
    int e0 = in_sizes[1];
    int e1 = in_sizes[4];
    int emax = e0 > e1 ? e0 : e1;

    dim3 gN((n + 511) / 512, 2);
    dim3 gE8(((emax + 7) / 8 + 511) / 512, 2);
    dim3 gF((n * HW + 255) / 256, 2);

    k_init<<<gN, 512>>>(n);
    k_count<<<gE8, 512>>>(dst_p, dst_s, e0, e1);
    k_scan<<<2, 1024>>>(n);
    k_fill<<<gE8, 512>>>(src_p, dst_p, src_s, dst_s, e0, e1);
    k_feat2h<<<gF, 256>>>(feat_p, feat_s, n);

    dim3 gL((n + T - 1) / T, 2);
    k_layer<<<gL, 128>>>(0, 1, W[0], b[0], n, 0);   // feat(fp8) -> buf1
    k_layer<<<gL, 128>>>(1, 0, W[1], b[1], n, 0);   // buf1 -> buf0
    k_layer<<<gL, 128>>>(0, 1, W[2], b[2], n, 1);   // buf0 -> colsum only

    k_match<<<1, 256>>>(Wr, br, Wm1, bm1, Wm2, bm2, (float)n, (float*)d_out);
}